// round 8
// baseline (speedup 1.0000x reference)
#include <cuda_runtime.h>
#include <cuda_fp16.h>
#include <math.h>
#include <stdint.h>

// ---------------------------------------------------------------------------
// SpectralDiscriminator on GB300 — fp16 mma.sync + 3-stage cp.async pipeline.
// R8: smem-staged transposed store (v conv), merged q|k GEMM, dynamic k-steps.
// ---------------------------------------------------------------------------

#define NPIX 4096
#define BATCH 4

__device__ __half g_inT[BATCH * NPIX * 8];
__device__ __half g_a1 [BATCH * NPIX * 64];
__device__ __half g_a2 [BATCH * NPIX * 128];
__device__ __half g_a3 [BATCH * NPIX * 256];
__device__ __half g_qk [BATCH * NPIX * 128];          // [pix][2Cq]
__device__ __half g_v  [BATCH * 512 * NPIX];          // channel-major [c][pix]
__device__ __half g_E  [(size_t)BATCH * NPIX * NPIX]; // 128 MB
__device__ __half g_t1 [BATCH * NPIX * 256];
__device__ __half g_t2 [BATCH * NPIX * 512];
__device__ __half g_a4 [BATCH * NPIX * 512];
__device__ float g_a3f[BATCH * NPIX * 256];
__device__ float g_a4f[BATCH * NPIX * 512];
__device__ float g_sig[8];
__device__ float g_qkb1[64];
__device__ float g_qkb2[128];
// fp16 weights (spectral scale folded into W1..W5)
__device__ __half g_W1h[64 * 8];
__device__ __half g_W2h[128 * 64];
__device__ __half g_W3h[256 * 128];
__device__ __half g_W4h[512 * 256];
__device__ __half g_W5h[1 * 512];
__device__ __half g_qkW1h[64 * 256];     // [q;k] concat
__device__ __half g_vW1h[256 * 256];
__device__ __half g_qkW2h[128 * 512];
__device__ __half g_vW2h[512 * 512];

__device__ __forceinline__ uint32_t smem_u32(const void* p) {
    uint32_t a;
    asm("{ .reg .u64 t; cvta.to.shared.u64 t, %1; cvt.u32.u64 %0, t; }" : "=r"(a) : "l"(p));
    return a;
}

// cp.async one 128-row x 64-half tile into SW128 smem (128B rows, 8x16B chunks)
__device__ __forceinline__ void cpa_tile(uint32_t dstBase, const __half* src, int ld,
                                         int Rall, int r0, int K, int k0, int tid) {
    #pragma unroll
    for (int i = 0; i < 4; i++) {
        int e = tid + i * 256;
        int r = e >> 3, c = e & 7;
        int gr = r0 + r;
        uint32_t dst = dstBase + r * 128 + ((c ^ (r & 7)) << 4);
        bool ok = (gr < Rall) && (k0 + c * 8 < K);
        const __half* g = src + (ok ? ((size_t)gr * ld + k0 + c * 8) : 0);
        int bytes = ok ? 16 : 0;
        asm volatile("cp.async.cg.shared.global [%0], [%1], 16, %2;\n"
                     :: "r"(dst), "l"(g), "r"(bytes));
    }
}

// ---------------------------------------------------------------------------
// fp16 GEMM: C[m][n] = sum_k A[m,k]*B[n,k], K-major fp16, tile 128x128x64,
// 3-stage cp.async pipeline, ldmatrix fragments, f32 accumulate.
// EPI: 0 leaky(acc+bias[n]) -> fp16 (+f32 copy if WF32)
//      1 acc+bias[n] -> fp16
//      2 acc -> fp16 (energy)
//      3 gamma*acc + Resf32 -> fp16
//      4 acc+bias[n] -> fp16, transposed store C[n*NPIX+m] via smem bounce
//      5 leaky(acc+bias[n]) -> f32
// ---------------------------------------------------------------------------
template<int EPI, int WF32>
__global__ void __launch_bounds__(256, 2)
hgemm(const __half* __restrict__ A, const __half* __restrict__ B,
      __half* __restrict__ Ch, float* __restrict__ Cf,
      int Mall, int Nall, int K, int lda, int ldb, int ldc,
      size_t sA, size_t sB, size_t sC, size_t sCf, size_t sR,
      const float* __restrict__ bias, const float* __restrict__ gammaP,
      const float* __restrict__ Res)
{
    extern __shared__ char smem[];
    uint32_t sbase = smem_u32(smem);
    const uint32_t stageSz = 32768;     // A 16KB + B 16KB per stage, 3 stages

    int tid = threadIdx.x, lane = tid & 31, wid = tid >> 5;
    int bz = blockIdx.z;
    A += sA * bz;  B += sB * bz;

    int m0 = blockIdx.x * 128;
    int n0 = blockIdx.y * 128;
    int wm = (wid & 3) * 32;
    int wn = (wid >> 2) * 64;

    float acc[2][8][4];
    #pragma unroll
    for (int a = 0; a < 2; a++)
        #pragma unroll
        for (int b = 0; b < 8; b++)
            #pragma unroll
            for (int c = 0; c < 4; c++) acc[a][b][c] = 0.f;

    int nkt = (K + 63) >> 6;

    // prologue: stages 0,1
    #pragma unroll
    for (int s = 0; s < 2; s++) {
        if (s < nkt) {
            uint32_t b = sbase + s * stageSz;
            cpa_tile(b, A, lda, Mall, m0, K, s * 64, tid);
            cpa_tile(b + 16384, B, ldb, Nall, n0, K, s * 64, tid);
        }
        asm volatile("cp.async.commit_group;\n");
    }

    for (int kt = 0; kt < nkt; kt++) {
        asm volatile("cp.async.wait_group 1;\n");
        __syncthreads();

        int bufi = kt % 3;
        uint32_t Ab = sbase + bufi * stageSz;
        uint32_t Bb = Ab + 16384;

        int kl = K - kt * 64;
        int nks = (kl >= 64) ? 4 : ((kl + 15) >> 4);

        #pragma unroll 4
        for (int ks = 0; ks < nks; ks++) {
            int c0 = ks * 2;
            uint32_t af[2][4];
            #pragma unroll
            for (int mt = 0; mt < 2; mt++) {
                int lr = wm + mt * 16 + (lane & 15);
                int lc = c0 + (lane >> 4);
                uint32_t ad = Ab + lr * 128 + ((lc ^ (lr & 7)) << 4);
                asm volatile("ldmatrix.sync.aligned.m8n8.x4.shared.b16 {%0,%1,%2,%3}, [%4];\n"
                    : "=r"(af[mt][0]), "=r"(af[mt][1]), "=r"(af[mt][2]), "=r"(af[mt][3])
                    : "r"(ad));
            }
            uint32_t bf[8][2];
            #pragma unroll
            for (int j = 0; j < 4; j++) {
                int nb_ = wn + j * 16;
                int lr = nb_ + (lane & 7) + ((lane >> 4) << 3);
                int lc = c0 + ((lane >> 3) & 1);
                uint32_t bd = Bb + lr * 128 + ((lc ^ (lr & 7)) << 4);
                asm volatile("ldmatrix.sync.aligned.m8n8.x4.shared.b16 {%0,%1,%2,%3}, [%4];\n"
                    : "=r"(bf[2*j][0]), "=r"(bf[2*j][1]), "=r"(bf[2*j+1][0]), "=r"(bf[2*j+1][1])
                    : "r"(bd));
            }
            #pragma unroll
            for (int mt = 0; mt < 2; mt++)
                #pragma unroll
                for (int nt = 0; nt < 8; nt++)
                    asm volatile("mma.sync.aligned.m16n8k16.row.col.f32.f16.f16.f32 "
                        "{%0,%1,%2,%3}, {%4,%5,%6,%7}, {%8,%9}, {%0,%1,%2,%3};\n"
                        : "+f"(acc[mt][nt][0]), "+f"(acc[mt][nt][1]),
                          "+f"(acc[mt][nt][2]), "+f"(acc[mt][nt][3])
                        : "r"(af[mt][0]), "r"(af[mt][1]), "r"(af[mt][2]), "r"(af[mt][3]),
                          "r"(bf[nt][0]), "r"(bf[nt][1]));
        }

        // issue stage kt+2
        int nx = kt + 2;
        if (nx < nkt) {
            uint32_t b = sbase + (nx % 3) * stageSz;
            cpa_tile(b, A, lda, Mall, m0, K, nx * 64, tid);
            cpa_tile(b + 16384, B, ldb, Nall, n0, K, nx * 64, tid);
        }
        asm volatile("cp.async.commit_group;\n");
    }

    // ---- epilogue
    __half* Cp = Ch + sC * bz;
    float*  Cfp = Cf + sCf * bz;
    const float* Rp = (EPI == 3) ? (Res + sR * bz) : nullptr;
    float gam = (EPI == 3) ? *gammaP : 0.f;
    int g = lane >> 2, tg = lane & 3;

    if (EPI == 4) {
        // transpose via smem: st[col][132] f32, then coalesced fp16 row writes
        asm volatile("cp.async.wait_group 0;\n");
        __syncthreads();
        float* st = (float*)smem;
        #pragma unroll
        for (int mt = 0; mt < 2; mt++)
        #pragma unroll
        for (int h = 0; h < 2; h++) {
            int rl = wm + mt * 16 + g + h * 8;
            #pragma unroll
            for (int nt = 0; nt < 8; nt++) {
                int cl = wn + nt * 8 + tg * 2;
                st[cl * 132 + rl]       = acc[mt][nt][h * 2 + 0] + bias[n0 + cl];
                st[(cl + 1) * 132 + rl] = acc[mt][nt][h * 2 + 1] + bias[n0 + cl + 1];
            }
        }
        __syncthreads();
        int c = tid >> 1, ch = tid & 1;
        uint4 hb[8];
        __half* hbh = (__half*)hb;
        const float* sp = st + c * 132 + ch * 64;
        #pragma unroll
        for (int j = 0; j < 32; j++)
            ((__half2*)hbh)[j] = __floats2half2_rn(sp[2 * j], sp[2 * j + 1]);
        uint4* dp = (uint4*)&Cp[(size_t)(n0 + c) * NPIX + m0 + ch * 64];
        #pragma unroll
        for (int jj = 0; jj < 8; jj++) dp[jj] = hb[jj];
        return;
    }

    #pragma unroll
    for (int mt = 0; mt < 2; mt++)
    #pragma unroll
    for (int h = 0; h < 2; h++) {
        int row = m0 + wm + mt * 16 + g + h * 8;
        #pragma unroll
        for (int nt = 0; nt < 8; nt++) {
            int col = n0 + wn + nt * 8 + tg * 2;
            float v0 = acc[mt][nt][h * 2 + 0];
            float v1 = acc[mt][nt][h * 2 + 1];
            if (EPI == 0 || EPI == 5) {
                if (col < Nall)     { v0 += bias[col];     v0 = v0 > 0.f ? v0 : 0.1f * v0; }
                if (col + 1 < Nall) { v1 += bias[col + 1]; v1 = v1 > 0.f ? v1 : 0.1f * v1; }
            } else if (EPI == 1) {
                if (col < Nall)     v0 += bias[col];
                if (col + 1 < Nall) v1 += bias[col + 1];
            } else if (EPI == 3) {
                if (col < Nall) {
                    const float* rp = Rp + (size_t)row * ldc + col;
                    v0 = gam * v0 + rp[0];
                    v1 = gam * v1 + rp[1];
                }
            }
            if (EPI == 5) {
                if (col < Nall)     Cfp[(size_t)row * ldc + col]     = v0;
                if (col + 1 < Nall) Cfp[(size_t)row * ldc + col + 1] = v1;
            } else {
                if (col < Nall) {   // Nall even at all fp16 call sites
                    *(__half2*)&Cp[(size_t)row * ldc + col] = __floats2half2_rn(v0, v1);
                    if (WF32)
                        *(float2*)&Cfp[(size_t)row * ldc + col] = make_float2(v0, v1);
                }
            }
        }
    }
}

// ---------------------------------------------------------------------------
// spectral norms (all 5, one block each)
// ---------------------------------------------------------------------------
__global__ void snorm_all(const float* __restrict__ W1, const float* __restrict__ u1,
                          const float* __restrict__ W2, const float* __restrict__ u2,
                          const float* __restrict__ W3, const float* __restrict__ u3,
                          const float* __restrict__ W4, const float* __restrict__ u4,
                          const float* __restrict__ W5, const float* __restrict__ u5,
                          float* __restrict__ sig)
{
    __shared__ float vs[512];
    __shared__ float us[512];
    __shared__ float red[256];
    __shared__ float red8[8];

    const float* W; const float* u; int O, C;
    switch (blockIdx.x) {
        case 0: W = W1; u = u1; O = 64;  C = 6;   break;
        case 1: W = W2; u = u2; O = 128; C = 64;  break;
        case 2: W = W3; u = u3; O = 256; C = 128; break;
        case 3: W = W4; u = u4; O = 512; C = 256; break;
        default: W = W5; u = u5; O = 1;  C = 512; break;
    }
    int t = threadIdx.x, lane = t & 31, wid = t >> 5;

    for (int o = t; o < O; o += 256) us[o] = u[o];
    __syncthreads();
    for (int c = t; c < C; c += 256) {
        float s = 0.f;
        #pragma unroll 4
        for (int o = 0; o < O; o++) s += W[(size_t)o * C + c] * us[o];
        vs[c] = s;
    }
    __syncthreads();
    float s = 0.f;
    for (int c = t; c < C; c += 256) s += vs[c] * vs[c];
    red[t] = s; __syncthreads();
    for (int off = 128; off > 0; off >>= 1) { if (t < off) red[t] += red[t + off]; __syncthreads(); }
    float vinv = 1.f / (sqrtf(red[0]) + 1e-12f);
    __syncthreads();
    for (int c = t; c < C; c += 256) vs[c] *= vinv;
    __syncthreads();
    float accq = 0.f;
    for (int o = wid; o < O; o += 8) {
        float tv = 0.f;
        for (int c = lane; c < C; c += 32) tv += W[(size_t)o * C + c] * vs[c];
        #pragma unroll
        for (int off = 16; off > 0; off >>= 1) tv += __shfl_xor_sync(0xffffffffu, tv, off);
        if (lane == 0) accq += tv * tv;
    }
    if (lane == 0) red8[wid] = accq;
    __syncthreads();
    if (t == 0) {
        float S = 0.f;
        #pragma unroll
        for (int w = 0; w < 8; w++) S += red8[w];
        float sigma = S / (sqrtf(S) + 1e-12f);
        sig[blockIdx.x] = 1.f / sigma;
    }
}

// ---------------------------------------------------------------------------
// weight conversion f32 -> fp16 (scaled for W1..W5), K zero-padded, q|k concat
// ---------------------------------------------------------------------------
__global__ void wprep(const float* W1, const float* W2, const float* W3,
                      const float* W4, const float* W5,
                      const float* q1, const float* k1, const float* v1,
                      const float* q2, const float* k2, const float* v2,
                      const float* sig,
                      __half* o0, __half* o1, __half* o2, __half* o3, __half* o4,
                      __half* qk1, __half* vv1, __half* qk2, __half* vv2)
{
    const float* src; __half* dst; int O, C, Cp; float s = 1.f;
    switch (blockIdx.x) {
        case 0:  src = W1; dst = o0;             O = 64;  C = 6;   Cp = 8;   s = sig[0]; break;
        case 1:  src = W2; dst = o1;             O = 128; C = 64;  Cp = 64;  s = sig[1]; break;
        case 2:  src = W3; dst = o2;             O = 256; C = 128; Cp = 128; s = sig[2]; break;
        case 3:  src = W4; dst = o3;             O = 512; C = 256; Cp = 256; s = sig[3]; break;
        case 4:  src = W5; dst = o4;             O = 1;   C = 512; Cp = 512; s = sig[4]; break;
        case 5:  src = q1; dst = qk1;            O = 32;  C = 256; Cp = 256; break;
        case 6:  src = k1; dst = qk1 + 32 * 256; O = 32;  C = 256; Cp = 256; break;
        case 7:  src = v1; dst = vv1;            O = 256; C = 256; Cp = 256; break;
        case 8:  src = q2; dst = qk2;            O = 64;  C = 512; Cp = 512; break;
        case 9:  src = k2; dst = qk2 + 64 * 512; O = 64;  C = 512; Cp = 512; break;
        default: src = v2; dst = vv2;            O = 512; C = 512; Cp = 512; break;
    }
    int total = O * Cp;
    for (int i = blockIdx.y * 256 + threadIdx.x; i < total; i += 8 * 256) {
        int o = i / Cp, c = i % Cp;
        float v = (c < C) ? src[(size_t)o * C + c] * s : 0.f;
        dst[i] = __float2half(v);
    }
}

__global__ void biascat(const float* qb1, const float* kb1,
                        const float* qb2, const float* kb2,
                        float* d1, float* d2) {
    int t = threadIdx.x;
    if (t < 32) d1[t] = qb1[t];
    else if (t < 64) d1[t] = kb1[t - 32];
    if (t < 64) d2[t] = qb2[t];
    else d2[t] = kb2[t - 64];
}

// ---------------------------------------------------------------------------
// input transpose: (B,6,64,64) f32 -> [b][pix][8] fp16
// ---------------------------------------------------------------------------
__global__ void tin(const float* __restrict__ in, __half* __restrict__ out) {
    int b = blockIdx.y;
    int p = blockIdx.x * 256 + threadIdx.x;
    const float* s = in + (size_t)b * 6 * NPIX + p;
    __half h[8];
    #pragma unroll
    for (int c = 0; c < 6; c++) h[c] = __float2half(s[(size_t)c * NPIX]);
    h[6] = __float2half(0.f);
    h[7] = __float2half(0.f);
    *(uint4*)(out + ((size_t)b * NPIX + p) * 8) = *(uint4*)h;
}

// ---------------------------------------------------------------------------
// fp16 row softmax (rows of 4096), f32 math
// ---------------------------------------------------------------------------
__global__ void softmax_h(__half* __restrict__ E) {
    __shared__ float rm[256], rs[256];
    __half2* row = (__half2*)(E + (size_t)blockIdx.x * NPIX);
    int t = threadIdx.x;

    float mx = -3.0e38f, sm = 0.f;
    #pragma unroll
    for (int i = t; i < NPIX / 2; i += 256) {
        float2 v = __half22float2(row[i]);
        float m2 = fmaxf(v.x, v.y);
        if (m2 > mx) { sm *= __expf(mx - m2); mx = m2; }
        sm += __expf(v.x - mx) + __expf(v.y - mx);
    }
    rm[t] = mx; rs[t] = sm; __syncthreads();
    for (int off = 128; off > 0; off >>= 1) {
        if (t < off) {
            float m1 = rm[t], m2 = rm[t + off];
            float M = fmaxf(m1, m2);
            rs[t] = rs[t] * __expf(m1 - M) + rs[t + off] * __expf(m2 - M);
            rm[t] = M;
        }
        __syncthreads();
    }
    float M = rm[0];
    float inv = 1.f / rs[0];

    #pragma unroll
    for (int i = t; i < NPIX / 2; i += 256) {
        float2 v = __half22float2(row[i]);
        row[i] = __floats2half2_rn(__expf(v.x - M) * inv, __expf(v.y - M) * inv);
    }
}

// ---------------------------------------------------------------------------
// kernel_launch
// ---------------------------------------------------------------------------
extern "C" void kernel_launch(void* const* d_in, const int* in_sizes, int n_in,
                              void* d_out, int out_size)
{
    const float* inp  = (const float*)d_in[0];
    const float* W1 = (const float*)d_in[1];  const float* b1 = (const float*)d_in[2];  const float* u1 = (const float*)d_in[3];
    const float* W2 = (const float*)d_in[4];  const float* b2 = (const float*)d_in[5];  const float* u2 = (const float*)d_in[6];
    const float* W3 = (const float*)d_in[7];  const float* b3 = (const float*)d_in[8];  const float* u3 = (const float*)d_in[9];
    const float* W4 = (const float*)d_in[10]; const float* b4 = (const float*)d_in[11]; const float* u4 = (const float*)d_in[12];
    const float* W5 = (const float*)d_in[13]; const float* b5 = (const float*)d_in[14]; const float* u5 = (const float*)d_in[15];
    const float* a1qW = (const float*)d_in[16]; const float* a1qb = (const float*)d_in[17];
    const float* a1kW = (const float*)d_in[18]; const float* a1kb = (const float*)d_in[19];
    const float* a1vW = (const float*)d_in[20]; const float* a1vb = (const float*)d_in[21];
    const float* a1g  = (const float*)d_in[22];
    const float* a2qW = (const float*)d_in[23]; const float* a2qb = (const float*)d_in[24];
    const float* a2kW = (const float*)d_in[25]; const float* a2kb = (const float*)d_in[26];
    const float* a2vW = (const float*)d_in[27]; const float* a2vb = (const float*)d_in[28];
    const float* a2g  = (const float*)d_in[29];

    __half *inTh, *a1h, *a2h, *a3h, *qkh, *vh, *Eh, *t1h, *t2h, *a4h;
    __half *W1h, *W2h, *W3h, *W4h, *W5h, *qkW1h, *vW1h, *qkW2h, *vW2h;
    float *a3f, *a4f, *sig, *qkb1, *qkb2;
    cudaGetSymbolAddress((void**)&inTh, g_inT);
    cudaGetSymbolAddress((void**)&a1h, g_a1);
    cudaGetSymbolAddress((void**)&a2h, g_a2);
    cudaGetSymbolAddress((void**)&a3h, g_a3);
    cudaGetSymbolAddress((void**)&qkh, g_qk);
    cudaGetSymbolAddress((void**)&vh,  g_v);
    cudaGetSymbolAddress((void**)&Eh,  g_E);
    cudaGetSymbolAddress((void**)&t1h, g_t1);
    cudaGetSymbolAddress((void**)&t2h, g_t2);
    cudaGetSymbolAddress((void**)&a4h, g_a4);
    cudaGetSymbolAddress((void**)&a3f, g_a3f);
    cudaGetSymbolAddress((void**)&a4f, g_a4f);
    cudaGetSymbolAddress((void**)&sig, g_sig);
    cudaGetSymbolAddress((void**)&qkb1, g_qkb1);
    cudaGetSymbolAddress((void**)&qkb2, g_qkb2);
    cudaGetSymbolAddress((void**)&W1h, g_W1h);
    cudaGetSymbolAddress((void**)&W2h, g_W2h);
    cudaGetSymbolAddress((void**)&W3h, g_W3h);
    cudaGetSymbolAddress((void**)&W4h, g_W4h);
    cudaGetSymbolAddress((void**)&W5h, g_W5h);
    cudaGetSymbolAddress((void**)&qkW1h, g_qkW1h);
    cudaGetSymbolAddress((void**)&vW1h, g_vW1h);
    cudaGetSymbolAddress((void**)&qkW2h, g_qkW2h);
    cudaGetSymbolAddress((void**)&vW2h, g_vW2h);

    const int SMEMSZ = 98304;   // 3 stages x 32KB
    cudaFuncSetAttribute(hgemm<0,0>, cudaFuncAttributeMaxDynamicSharedMemorySize, SMEMSZ);
    cudaFuncSetAttribute(hgemm<0,1>, cudaFuncAttributeMaxDynamicSharedMemorySize, SMEMSZ);
    cudaFuncSetAttribute(hgemm<1,0>, cudaFuncAttributeMaxDynamicSharedMemorySize, SMEMSZ);
    cudaFuncSetAttribute(hgemm<2,0>, cudaFuncAttributeMaxDynamicSharedMemorySize, SMEMSZ);
    cudaFuncSetAttribute(hgemm<3,0>, cudaFuncAttributeMaxDynamicSharedMemorySize, SMEMSZ);
    cudaFuncSetAttribute(hgemm<4,0>, cudaFuncAttributeMaxDynamicSharedMemorySize, SMEMSZ);
    cudaFuncSetAttribute(hgemm<5,0>, cudaFuncAttributeMaxDynamicSharedMemorySize, SMEMSZ);

    const size_t NP = NPIX;
    const size_t NN = NP * NP;
    auto gd = [&](int Nn) { return dim3(NPIX / 128, (Nn + 127) / 128, BATCH); };

    snorm_all<<<5, 256>>>(W1, u1, W2, u2, W3, u3, W4, u4, W5, u5, sig);
    wprep<<<dim3(11, 8), 256>>>(W1, W2, W3, W4, W5, a1qW, a1kW, a1vW, a2qW, a2kW, a2vW,
                                sig, W1h, W2h, W3h, W4h, W5h, qkW1h, vW1h, qkW2h, vW2h);
    biascat<<<1, 128>>>(a1qb, a1kb, a2qb, a2kb, qkb1, qkb2);
    tin<<<dim3(16, BATCH), 256>>>(inp, inTh);

    // conv1/2/3
    hgemm<0,0><<<gd(64), 256, SMEMSZ>>>(inTh, W1h, a1h, nullptr, NPIX, 64, 8, 8, 8, 64,
        NP * 8, 0, NP * 64, 0, 0, b1, nullptr, nullptr);
    hgemm<0,0><<<gd(128), 256, SMEMSZ>>>(a1h, W2h, a2h, nullptr, NPIX, 128, 64, 64, 64, 128,
        NP * 64, 0, NP * 128, 0, 0, b2, nullptr, nullptr);
    hgemm<0,1><<<gd(256), 256, SMEMSZ>>>(a2h, W3h, a3h, a3f, NPIX, 256, 128, 128, 128, 256,
        NP * 128, 0, NP * 256, NP * 256, 0, b3, nullptr, nullptr);

    // attention 1 (C=256, Cq=32)
    hgemm<1,0><<<gd(64), 256, SMEMSZ>>>(a3h, qkW1h, qkh, nullptr, NPIX, 64, 256, 256, 256, 64,
        NP * 256, 0, NP * 64, 0, 0, qkb1, nullptr, nullptr);
    hgemm<4,0><<<gd(256), 256, SMEMSZ>>>(a3h, vW1h, vh, nullptr, NPIX, 256, 256, 256, 256, NPIX,
        NP * 256, 0, 256 * NP, 0, 0, a1vb, nullptr, nullptr);
    hgemm<2,0><<<gd(4096), 256, SMEMSZ>>>(qkh, qkh + 32, Eh, nullptr, NPIX, 4096, 32, 64, 64, 4096,
        NP * 64, NP * 64, NN, 0, 0, nullptr, nullptr, nullptr);
    softmax_h<<<BATCH * NPIX, 256>>>(Eh);
    hgemm<3,0><<<gd(256), 256, SMEMSZ>>>(Eh, vh, t1h, nullptr, NPIX, 256, 4096, 4096, 4096, 256,
        NN, 256 * NP, NP * 256, 0, NP * 256, nullptr, a1g, a3f);

    // conv4
    hgemm<0,1><<<gd(512), 256, SMEMSZ>>>(t1h, W4h, a4h, a4f, NPIX, 512, 256, 256, 256, 512,
        NP * 256, 0, NP * 512, NP * 512, 0, b4, nullptr, nullptr);

    // attention 2 (C=512, Cq=64)
    hgemm<1,0><<<gd(128), 256, SMEMSZ>>>(a4h, qkW2h, qkh, nullptr, NPIX, 128, 512, 512, 512, 128,
        NP * 512, 0, NP * 128, 0, 0, qkb2, nullptr, nullptr);
    hgemm<4,0><<<gd(512), 256, SMEMSZ>>>(a4h, vW2h, vh, nullptr, NPIX, 512, 512, 512, 512, NPIX,
        NP * 512, 0, 512 * NP, 0, 0, a2vb, nullptr, nullptr);
    hgemm<2,0><<<gd(4096), 256, SMEMSZ>>>(qkh, qkh + 64, Eh, nullptr, NPIX, 4096, 64, 128, 128, 4096,
        NP * 128, NP * 128, NN, 0, 0, nullptr, nullptr, nullptr);
    softmax_h<<<BATCH * NPIX, 256>>>(Eh);
    hgemm<3,0><<<gd(512), 256, SMEMSZ>>>(Eh, vh, t2h, nullptr, NPIX, 512, 4096, 4096, 4096, 512,
        NN, 512 * NP, NP * 512, 0, NP * 512, nullptr, a2g, a4f);

    // conv5 -> f32 output (B, 4096)
    hgemm<5,0><<<gd(1), 256, SMEMSZ>>>(t2h, W5h, nullptr, (float*)d_out, NPIX, 1, 512, 512, 512, 1,
        NP * 512, 0, 0, NP, 0, b5, nullptr, nullptr);
}

// round 9
// speedup vs baseline: 1.1234x; 1.1234x over previous
#include <cuda_runtime.h>
#include <cuda_fp16.h>
#include <math.h>
#include <stdint.h>

// ---------------------------------------------------------------------------
// SpectralDiscriminator on GB300 — fp16 mma.sync GEMMs.
// R9: exp fused into energy epilogue (constant-shift softmax), rowsum kernel +
// 1/sum folded into aw epilogue, n-tile-fastest raster for A-operand reuse.
// ---------------------------------------------------------------------------

#define NPIX 4096
#define BATCH 4
#define ESHIFT 4.0f

__device__ __half g_inT[BATCH * NPIX * 8];
__device__ __half g_a1 [BATCH * NPIX * 64];
__device__ __half g_a2 [BATCH * NPIX * 128];
__device__ __half g_a3 [BATCH * NPIX * 256];
__device__ __half g_qk [BATCH * NPIX * 128];          // [pix][2Cq]
__device__ __half g_v  [BATCH * 512 * NPIX];          // channel-major [c][pix]
__device__ __half g_E  [(size_t)BATCH * NPIX * NPIX]; // expE, 128 MB
__device__ __half g_t1 [BATCH * NPIX * 256];
__device__ __half g_t2 [BATCH * NPIX * 512];
__device__ __half g_a4 [BATCH * NPIX * 512];
__device__ float g_a3f[BATCH * NPIX * 256];
__device__ float g_a4f[BATCH * NPIX * 512];
__device__ float g_rs [BATCH * NPIX];                 // 1/rowsum
__device__ float g_sig[8];
__device__ float g_qkb1[64];
__device__ float g_qkb2[128];
__device__ __half g_W1h[64 * 8];
__device__ __half g_W2h[128 * 64];
__device__ __half g_W3h[256 * 128];
__device__ __half g_W4h[512 * 256];
__device__ __half g_W5h[1 * 512];
__device__ __half g_qkW1h[64 * 256];
__device__ __half g_vW1h[256 * 256];
__device__ __half g_qkW2h[128 * 512];
__device__ __half g_vW2h[512 * 512];

__device__ __forceinline__ uint32_t smem_u32(const void* p) {
    uint32_t a;
    asm("{ .reg .u64 t; cvta.to.shared.u64 t, %1; cvt.u32.u64 %0, t; }" : "=r"(a) : "l"(p));
    return a;
}

// cp.async one 128-row x 64-half tile into SW128 smem
__device__ __forceinline__ void cpa_tile(uint32_t dstBase, const __half* src, int ld,
                                         int Rall, int r0, int K, int k0, int tid) {
    #pragma unroll
    for (int i = 0; i < 4; i++) {
        int e = tid + i * 256;
        int r = e >> 3, c = e & 7;
        int gr = r0 + r;
        uint32_t dst = dstBase + r * 128 + ((c ^ (r & 7)) << 4);
        bool ok = (gr < Rall) && (k0 + c * 8 < K);
        const __half* g = src + (ok ? ((size_t)gr * ld + k0 + c * 8) : 0);
        int bytes = ok ? 16 : 0;
        asm volatile("cp.async.cg.shared.global [%0], [%1], 16, %2;\n"
                     :: "r"(dst), "l"(g), "r"(bytes));
    }
}

// ---------------------------------------------------------------------------
// fp16 GEMM: C[m][n] = sum_k A[m,k]*B[n,k]. Grid: x = n-tile (fast), y = m-tile.
// EPI: 0 leaky(acc+bias[n]) -> fp16 (+f32 copy if WF32)
//      1 acc+bias[n] -> fp16
//      3 gamma*acc*rinv[m] + Resf32 -> fp16         (aw; bias carries 1/rowsum)
//      4 acc+bias[n] -> fp16 transposed via smem bounce (v conv)
//      5 leaky(acc+bias[n]) -> f32
//      6 exp(acc - ESHIFT) -> fp16                  (energy)
// ---------------------------------------------------------------------------
template<int EPI, int WF32>
__global__ void __launch_bounds__(256, 2)
hgemm(const __half* __restrict__ A, const __half* __restrict__ B,
      __half* __restrict__ Ch, float* __restrict__ Cf,
      int Mall, int Nall, int K, int lda, int ldb, int ldc,
      size_t sA, size_t sB, size_t sC, size_t sCf, size_t sR,
      const float* __restrict__ bias, const float* __restrict__ gammaP,
      const float* __restrict__ Res)
{
    extern __shared__ char smem[];
    uint32_t sbase = smem_u32(smem);
    const uint32_t stageSz = 32768;

    int tid = threadIdx.x, lane = tid & 31, wid = tid >> 5;
    int bz = blockIdx.z;
    A += sA * bz;  B += sB * bz;

    int m0 = blockIdx.y * 128;
    int n0 = blockIdx.x * 128;
    int wm = (wid & 3) * 32;
    int wn = (wid >> 2) * 64;

    float acc[2][8][4];
    #pragma unroll
    for (int a = 0; a < 2; a++)
        #pragma unroll
        for (int b = 0; b < 8; b++)
            #pragma unroll
            for (int c = 0; c < 4; c++) acc[a][b][c] = 0.f;

    int nkt = (K + 63) >> 6;

    #pragma unroll
    for (int s = 0; s < 2; s++) {
        if (s < nkt) {
            uint32_t b = sbase + s * stageSz;
            cpa_tile(b, A, lda, Mall, m0, K, s * 64, tid);
            cpa_tile(b + 16384, B, ldb, Nall, n0, K, s * 64, tid);
        }
        asm volatile("cp.async.commit_group;\n");
    }

    for (int kt = 0; kt < nkt; kt++) {
        asm volatile("cp.async.wait_group 1;\n");
        __syncthreads();

        int bufi = kt % 3;
        uint32_t Ab = sbase + bufi * stageSz;
        uint32_t Bb = Ab + 16384;

        int kl = K - kt * 64;
        int nks = (kl >= 64) ? 4 : ((kl + 15) >> 4);

        #pragma unroll 4
        for (int ks = 0; ks < nks; ks++) {
            int c0 = ks * 2;
            uint32_t af[2][4];
            #pragma unroll
            for (int mt = 0; mt < 2; mt++) {
                int lr = wm + mt * 16 + (lane & 15);
                int lc = c0 + (lane >> 4);
                uint32_t ad = Ab + lr * 128 + ((lc ^ (lr & 7)) << 4);
                asm volatile("ldmatrix.sync.aligned.m8n8.x4.shared.b16 {%0,%1,%2,%3}, [%4];\n"
                    : "=r"(af[mt][0]), "=r"(af[mt][1]), "=r"(af[mt][2]), "=r"(af[mt][3])
                    : "r"(ad));
            }
            uint32_t bf[8][2];
            #pragma unroll
            for (int j = 0; j < 4; j++) {
                int nb_ = wn + j * 16;
                int lr = nb_ + (lane & 7) + ((lane >> 4) << 3);
                int lc = c0 + ((lane >> 3) & 1);
                uint32_t bd = Bb + lr * 128 + ((lc ^ (lr & 7)) << 4);
                asm volatile("ldmatrix.sync.aligned.m8n8.x4.shared.b16 {%0,%1,%2,%3}, [%4];\n"
                    : "=r"(bf[2*j][0]), "=r"(bf[2*j][1]), "=r"(bf[2*j+1][0]), "=r"(bf[2*j+1][1])
                    : "r"(bd));
            }
            #pragma unroll
            for (int mt = 0; mt < 2; mt++)
                #pragma unroll
                for (int nt = 0; nt < 8; nt++)
                    asm volatile("mma.sync.aligned.m16n8k16.row.col.f32.f16.f16.f32 "
                        "{%0,%1,%2,%3}, {%4,%5,%6,%7}, {%8,%9}, {%0,%1,%2,%3};\n"
                        : "+f"(acc[mt][nt][0]), "+f"(acc[mt][nt][1]),
                          "+f"(acc[mt][nt][2]), "+f"(acc[mt][nt][3])
                        : "r"(af[mt][0]), "r"(af[mt][1]), "r"(af[mt][2]), "r"(af[mt][3]),
                          "r"(bf[nt][0]), "r"(bf[nt][1]));
        }

        int nx = kt + 2;
        if (nx < nkt) {
            uint32_t b = sbase + (nx % 3) * stageSz;
            cpa_tile(b, A, lda, Mall, m0, K, nx * 64, tid);
            cpa_tile(b + 16384, B, ldb, Nall, n0, K, nx * 64, tid);
        }
        asm volatile("cp.async.commit_group;\n");
    }

    // ---- epilogue
    __half* Cp = Ch + sC * bz;
    float*  Cfp = Cf + sCf * bz;
    const float* Rp = (EPI == 3) ? (Res + sR * bz) : nullptr;
    const float* rinv = (EPI == 3) ? (bias + (size_t)bz * NPIX) : nullptr;
    float gam = (EPI == 3) ? *gammaP : 0.f;
    int g = lane >> 2, tg = lane & 3;

    if (EPI == 4) {
        asm volatile("cp.async.wait_group 0;\n");
        __syncthreads();
        float* st = (float*)smem;
        #pragma unroll
        for (int mt = 0; mt < 2; mt++)
        #pragma unroll
        for (int h = 0; h < 2; h++) {
            int rl = wm + mt * 16 + g + h * 8;
            #pragma unroll
            for (int nt = 0; nt < 8; nt++) {
                int cl = wn + nt * 8 + tg * 2;
                st[cl * 132 + rl]       = acc[mt][nt][h * 2 + 0] + bias[n0 + cl];
                st[(cl + 1) * 132 + rl] = acc[mt][nt][h * 2 + 1] + bias[n0 + cl + 1];
            }
        }
        __syncthreads();
        int c = tid >> 1, ch = tid & 1;
        uint4 hb[8];
        __half* hbh = (__half*)hb;
        const float* sp = st + c * 132 + ch * 64;
        #pragma unroll
        for (int j = 0; j < 32; j++)
            ((__half2*)hbh)[j] = __floats2half2_rn(sp[2 * j], sp[2 * j + 1]);
        uint4* dp = (uint4*)&Cp[(size_t)(n0 + c) * NPIX + m0 + ch * 64];
        #pragma unroll
        for (int jj = 0; jj < 8; jj++) dp[jj] = hb[jj];
        return;
    }

    #pragma unroll
    for (int mt = 0; mt < 2; mt++)
    #pragma unroll
    for (int h = 0; h < 2; h++) {
        int row = m0 + wm + mt * 16 + g + h * 8;
        float is = (EPI == 3) ? gam * rinv[row] : 0.f;
        #pragma unroll
        for (int nt = 0; nt < 8; nt++) {
            int col = n0 + wn + nt * 8 + tg * 2;
            float v0 = acc[mt][nt][h * 2 + 0];
            float v1 = acc[mt][nt][h * 2 + 1];
            if (EPI == 0 || EPI == 5) {
                if (col < Nall)     { v0 += bias[col];     v0 = v0 > 0.f ? v0 : 0.1f * v0; }
                if (col + 1 < Nall) { v1 += bias[col + 1]; v1 = v1 > 0.f ? v1 : 0.1f * v1; }
            } else if (EPI == 1) {
                if (col < Nall)     v0 += bias[col];
                if (col + 1 < Nall) v1 += bias[col + 1];
            } else if (EPI == 3) {
                if (col < Nall) {
                    const float* rp = Rp + (size_t)row * ldc + col;
                    v0 = is * v0 + rp[0];
                    v1 = is * v1 + rp[1];
                }
            } else if (EPI == 6) {
                v0 = __expf(v0 - ESHIFT);
                v1 = __expf(v1 - ESHIFT);
            }
            if (EPI == 5) {
                if (col < Nall)     Cfp[(size_t)row * ldc + col]     = v0;
                if (col + 1 < Nall) Cfp[(size_t)row * ldc + col + 1] = v1;
            } else {
                if (col < Nall) {
                    *(__half2*)&Cp[(size_t)row * ldc + col] = __floats2half2_rn(v0, v1);
                    if (WF32)
                        *(float2*)&Cfp[(size_t)row * ldc + col] = make_float2(v0, v1);
                }
            }
        }
    }
}

// ---------------------------------------------------------------------------
// row sums of expE -> 1/sum (one warp per row, deterministic)
// ---------------------------------------------------------------------------
__global__ void rowsum(const __half* __restrict__ E, float* __restrict__ inv) {
    int r = blockIdx.x * 8 + (threadIdx.x >> 5);
    int lane = threadIdx.x & 31;
    const __half2* p = (const __half2*)(E + (size_t)r * NPIX);
    float s = 0.f;
    #pragma unroll 8
    for (int i = lane; i < NPIX / 2; i += 32) {
        float2 v = __half22float2(p[i]);
        s += v.x + v.y;
    }
    #pragma unroll
    for (int off = 16; off > 0; off >>= 1) s += __shfl_xor_sync(0xffffffffu, s, off);
    if (lane == 0) inv[r] = 1.f / s;
}

// ---------------------------------------------------------------------------
// spectral norms (all 5, one block each)
// ---------------------------------------------------------------------------
__global__ void snorm_all(const float* __restrict__ W1, const float* __restrict__ u1,
                          const float* __restrict__ W2, const float* __restrict__ u2,
                          const float* __restrict__ W3, const float* __restrict__ u3,
                          const float* __restrict__ W4, const float* __restrict__ u4,
                          const float* __restrict__ W5, const float* __restrict__ u5,
                          float* __restrict__ sig)
{
    __shared__ float vs[512];
    __shared__ float us[512];
    __shared__ float red[256];
    __shared__ float red8[8];

    const float* W; const float* u; int O, C;
    switch (blockIdx.x) {
        case 0: W = W1; u = u1; O = 64;  C = 6;   break;
        case 1: W = W2; u = u2; O = 128; C = 64;  break;
        case 2: W = W3; u = u3; O = 256; C = 128; break;
        case 3: W = W4; u = u4; O = 512; C = 256; break;
        default: W = W5; u = u5; O = 1;  C = 512; break;
    }
    int t = threadIdx.x, lane = t & 31, wid = t >> 5;

    for (int o = t; o < O; o += 256) us[o] = u[o];
    __syncthreads();
    for (int c = t; c < C; c += 256) {
        float s = 0.f;
        #pragma unroll 4
        for (int o = 0; o < O; o++) s += W[(size_t)o * C + c] * us[o];
        vs[c] = s;
    }
    __syncthreads();
    float s = 0.f;
    for (int c = t; c < C; c += 256) s += vs[c] * vs[c];
    red[t] = s; __syncthreads();
    for (int off = 128; off > 0; off >>= 1) { if (t < off) red[t] += red[t + off]; __syncthreads(); }
    float vinv = 1.f / (sqrtf(red[0]) + 1e-12f);
    __syncthreads();
    for (int c = t; c < C; c += 256) vs[c] *= vinv;
    __syncthreads();
    float accq = 0.f;
    for (int o = wid; o < O; o += 8) {
        float tv = 0.f;
        for (int c = lane; c < C; c += 32) tv += W[(size_t)o * C + c] * vs[c];
        #pragma unroll
        for (int off = 16; off > 0; off >>= 1) tv += __shfl_xor_sync(0xffffffffu, tv, off);
        if (lane == 0) accq += tv * tv;
    }
    if (lane == 0) red8[wid] = accq;
    __syncthreads();
    if (t == 0) {
        float S = 0.f;
        #pragma unroll
        for (int w = 0; w < 8; w++) S += red8[w];
        float sigma = S / (sqrtf(S) + 1e-12f);
        sig[blockIdx.x] = 1.f / sigma;
    }
}

// ---------------------------------------------------------------------------
// weight conversion f32 -> fp16 (scaled for W1..W5), K zero-padded, q|k concat
// ---------------------------------------------------------------------------
__global__ void wprep(const float* W1, const float* W2, const float* W3,
                      const float* W4, const float* W5,
                      const float* q1, const float* k1, const float* v1,
                      const float* q2, const float* k2, const float* v2,
                      const float* sig,
                      __half* o0, __half* o1, __half* o2, __half* o3, __half* o4,
                      __half* qk1, __half* vv1, __half* qk2, __half* vv2)
{
    const float* src; __half* dst; int O, C, Cp; float s = 1.f;
    switch (blockIdx.x) {
        case 0:  src = W1; dst = o0;             O = 64;  C = 6;   Cp = 8;   s = sig[0]; break;
        case 1:  src = W2; dst = o1;             O = 128; C = 64;  Cp = 64;  s = sig[1]; break;
        case 2:  src = W3; dst = o2;             O = 256; C = 128; Cp = 128; s = sig[2]; break;
        case 3:  src = W4; dst = o3;             O = 512; C = 256; Cp = 256; s = sig[3]; break;
        case 4:  src = W5; dst = o4;             O = 1;   C = 512; Cp = 512; s = sig[4]; break;
        case 5:  src = q1; dst = qk1;            O = 32;  C = 256; Cp = 256; break;
        case 6:  src = k1; dst = qk1 + 32 * 256; O = 32;  C = 256; Cp = 256; break;
        case 7:  src = v1; dst = vv1;            O = 256; C = 256; Cp = 256; break;
        case 8:  src = q2; dst = qk2;            O = 64;  C = 512; Cp = 512; break;
        case 9:  src = k2; dst = qk2 + 64 * 512; O = 64;  C = 512; Cp = 512; break;
        default: src = v2; dst = vv2;            O = 512; C = 512; Cp = 512; break;
    }
    int total = O * Cp;
    for (int i = blockIdx.y * 256 + threadIdx.x; i < total; i += 8 * 256) {
        int o = i / Cp, c = i % Cp;
        float v = (c < C) ? src[(size_t)o * C + c] * s : 0.f;
        dst[i] = __float2half(v);
    }
}

__global__ void biascat(const float* qb1, const float* kb1,
                        const float* qb2, const float* kb2,
                        float* d1, float* d2) {
    int t = threadIdx.x;
    if (t < 32) d1[t] = qb1[t];
    else if (t < 64) d1[t] = kb1[t - 32];
    if (t < 64) d2[t] = qb2[t];
    else d2[t] = kb2[t - 64];
}

__global__ void tin(const float* __restrict__ in, __half* __restrict__ out) {
    int b = blockIdx.y;
    int p = blockIdx.x * 256 + threadIdx.x;
    const float* s = in + (size_t)b * 6 * NPIX + p;
    __half h[8];
    #pragma unroll
    for (int c = 0; c < 6; c++) h[c] = __float2half(s[(size_t)c * NPIX]);
    h[6] = __float2half(0.f);
    h[7] = __float2half(0.f);
    *(uint4*)(out + ((size_t)b * NPIX + p) * 8) = *(uint4*)h;
}

// ---------------------------------------------------------------------------
// kernel_launch
// ---------------------------------------------------------------------------
extern "C" void kernel_launch(void* const* d_in, const int* in_sizes, int n_in,
                              void* d_out, int out_size)
{
    const float* inp  = (const float*)d_in[0];
    const float* W1 = (const float*)d_in[1];  const float* b1 = (const float*)d_in[2];  const float* u1 = (const float*)d_in[3];
    const float* W2 = (const float*)d_in[4];  const float* b2 = (const float*)d_in[5];  const float* u2 = (const float*)d_in[6];
    const float* W3 = (const float*)d_in[7];  const float* b3 = (const float*)d_in[8];  const float* u3 = (const float*)d_in[9];
    const float* W4 = (const float*)d_in[10]; const float* b4 = (const float*)d_in[11]; const float* u4 = (const float*)d_in[12];
    const float* W5 = (const float*)d_in[13]; const float* b5 = (const float*)d_in[14]; const float* u5 = (const float*)d_in[15];
    const float* a1qW = (const float*)d_in[16]; const float* a1qb = (const float*)d_in[17];
    const float* a1kW = (const float*)d_in[18]; const float* a1kb = (const float*)d_in[19];
    const float* a1vW = (const float*)d_in[20]; const float* a1vb = (const float*)d_in[21];
    const float* a1g  = (const float*)d_in[22];
    const float* a2qW = (const float*)d_in[23]; const float* a2qb = (const float*)d_in[24];
    const float* a2kW = (const float*)d_in[25]; const float* a2kb = (const float*)d_in[26];
    const float* a2vW = (const float*)d_in[27]; const float* a2vb = (const float*)d_in[28];
    const float* a2g  = (const float*)d_in[29];

    __half *inTh, *a1h, *a2h, *a3h, *qkh, *vh, *Eh, *t1h, *t2h, *a4h;
    __half *W1h, *W2h, *W3h, *W4h, *W5h, *qkW1h, *vW1h, *qkW2h, *vW2h;
    float *a3f, *a4f, *sig, *qkb1, *qkb2, *rs;
    cudaGetSymbolAddress((void**)&inTh, g_inT);
    cudaGetSymbolAddress((void**)&a1h, g_a1);
    cudaGetSymbolAddress((void**)&a2h, g_a2);
    cudaGetSymbolAddress((void**)&a3h, g_a3);
    cudaGetSymbolAddress((void**)&qkh, g_qk);
    cudaGetSymbolAddress((void**)&vh,  g_v);
    cudaGetSymbolAddress((void**)&Eh,  g_E);
    cudaGetSymbolAddress((void**)&t1h, g_t1);
    cudaGetSymbolAddress((void**)&t2h, g_t2);
    cudaGetSymbolAddress((void**)&a4h, g_a4);
    cudaGetSymbolAddress((void**)&a3f, g_a3f);
    cudaGetSymbolAddress((void**)&a4f, g_a4f);
    cudaGetSymbolAddress((void**)&sig, g_sig);
    cudaGetSymbolAddress((void**)&qkb1, g_qkb1);
    cudaGetSymbolAddress((void**)&qkb2, g_qkb2);
    cudaGetSymbolAddress((void**)&rs,  g_rs);
    cudaGetSymbolAddress((void**)&W1h, g_W1h);
    cudaGetSymbolAddress((void**)&W2h, g_W2h);
    cudaGetSymbolAddress((void**)&W3h, g_W3h);
    cudaGetSymbolAddress((void**)&W4h, g_W4h);
    cudaGetSymbolAddress((void**)&W5h, g_W5h);
    cudaGetSymbolAddress((void**)&qkW1h, g_qkW1h);
    cudaGetSymbolAddress((void**)&vW1h, g_vW1h);
    cudaGetSymbolAddress((void**)&qkW2h, g_qkW2h);
    cudaGetSymbolAddress((void**)&vW2h, g_vW2h);

    const int SMEMSZ = 98304;
    cudaFuncSetAttribute(hgemm<0,0>, cudaFuncAttributeMaxDynamicSharedMemorySize, SMEMSZ);
    cudaFuncSetAttribute(hgemm<0,1>, cudaFuncAttributeMaxDynamicSharedMemorySize, SMEMSZ);
    cudaFuncSetAttribute(hgemm<1,0>, cudaFuncAttributeMaxDynamicSharedMemorySize, SMEMSZ);
    cudaFuncSetAttribute(hgemm<3,0>, cudaFuncAttributeMaxDynamicSharedMemorySize, SMEMSZ);
    cudaFuncSetAttribute(hgemm<4,0>, cudaFuncAttributeMaxDynamicSharedMemorySize, SMEMSZ);
    cudaFuncSetAttribute(hgemm<5,0>, cudaFuncAttributeMaxDynamicSharedMemorySize, SMEMSZ);
    cudaFuncSetAttribute(hgemm<6,0>, cudaFuncAttributeMaxDynamicSharedMemorySize, SMEMSZ);

    const size_t NP = NPIX;
    const size_t NN = NP * NP;
    // x = n-tile (fast, shares A among consecutive CTAs), y = m-tile
    auto gd = [&](int Nn) { return dim3((Nn + 127) / 128, NPIX / 128, BATCH); };

    snorm_all<<<5, 256>>>(W1, u1, W2, u2, W3, u3, W4, u4, W5, u5, sig);
    wprep<<<dim3(11, 8), 256>>>(W1, W2, W3, W4, W5, a1qW, a1kW, a1vW, a2qW, a2kW, a2vW,
                                sig, W1h, W2h, W3h, W4h, W5h, qkW1h, vW1h, qkW2h, vW2h);
    biascat<<<1, 128>>>(a1qb, a1kb, a2qb, a2kb, qkb1, qkb2);
    tin<<<dim3(16, BATCH), 256>>>(inp, inTh);

    // conv1/2/3
    hgemm<0,0><<<gd(64), 256, SMEMSZ>>>(inTh, W1h, a1h, nullptr, NPIX, 64, 8, 8, 8, 64,
        NP * 8, 0, NP * 64, 0, 0, b1, nullptr, nullptr);
    hgemm<0,0><<<gd(128), 256, SMEMSZ>>>(a1h, W2h, a2h, nullptr, NPIX, 128, 64, 64, 64, 128,
        NP * 64, 0, NP * 128, 0, 0, b2, nullptr, nullptr);
    hgemm<0,1><<<gd(256), 256, SMEMSZ>>>(a2h, W3h, a3h, a3f, NPIX, 256, 128, 128, 128, 256,
        NP * 128, 0, NP * 256, NP * 256, 0, b3, nullptr, nullptr);

    // attention 1 (C=256, Cq=32)
    hgemm<1,0><<<gd(64), 256, SMEMSZ>>>(a3h, qkW1h, qkh, nullptr, NPIX, 64, 256, 256, 256, 64,
        NP * 256, 0, NP * 64, 0, 0, qkb1, nullptr, nullptr);
    hgemm<4,0><<<gd(256), 256, SMEMSZ>>>(a3h, vW1h, vh, nullptr, NPIX, 256, 256, 256, 256, NPIX,
        NP * 256, 0, 256 * NP, 0, 0, a1vb, nullptr, nullptr);
    hgemm<6,0><<<gd(4096), 256, SMEMSZ>>>(qkh, qkh + 32, Eh, nullptr, NPIX, 4096, 32, 64, 64, 4096,
        NP * 64, NP * 64, NN, 0, 0, nullptr, nullptr, nullptr);
    rowsum<<<BATCH * NPIX / 8, 256>>>(Eh, rs);
    hgemm<3,0><<<gd(256), 256, SMEMSZ>>>(Eh, vh, t1h, nullptr, NPIX, 256, 4096, 4096, 4096, 256,
        NN, 256 * NP, NP * 256, 0, NP * 256, rs, a1g, a3f);

    // conv4
    hgemm<0,1><<<gd(512), 256, SMEMSZ>>>(t1h, W4h, a4h, a4f, NPIX, 512, 256, 256, 256, 512,
        NP * 256, 0, NP * 512, NP * 512, 0, b4, nullptr, nullptr);

    // attention 2 (C=512, Cq=64)
    hgemm<1,0><<<gd(128), 256, SMEMSZ>>>(a4h, qkW2h, qkh, nullptr, NPIX, 128, 512, 512, 512, 128,
        NP * 512, 0, NP * 128, 0, 0, qkb2, nullptr, nullptr);
    hgemm<4,0><<<gd(512), 256, SMEMSZ>>>(a4h, vW2h, vh, nullptr, NPIX, 512, 512, 512, 512, NPIX,
        NP * 512, 0, 512 * NP, 0, 0, a2vb, nullptr, nullptr);
    hgemm<6,0><<<gd(4096), 256, SMEMSZ>>>(qkh, qkh + 64, Eh, nullptr, NPIX, 4096, 64, 128, 128, 4096,
        NP * 128, NP * 128, NN, 0, 0, nullptr, nullptr, nullptr);
    rowsum<<<BATCH * NPIX / 8, 256>>>(Eh, rs);
    hgemm<3,0><<<gd(512), 256, SMEMSZ>>>(Eh, vh, t2h, nullptr, NPIX, 512, 4096, 4096, 4096, 512,
        NN, 512 * NP, NP * 512, 0, NP * 512, rs, a2g, a4f);

    // conv5 -> f32 output (B, 4096)
    hgemm<5,0><<<gd(1), 256, SMEMSZ>>>(t2h, W5h, nullptr, (float*)d_out, NPIX, 1, 512, 512, 512, 1,
        NP * 512, 0, 0, NP, 0, b5, nullptr, nullptr);
}

// round 10
// speedup vs baseline: 1.1978x; 1.0662x over previous
#include <cuda_runtime.h>
#include <cuda_fp16.h>
#include <math.h>
#include <stdint.h>

// ---------------------------------------------------------------------------
// SpectralDiscriminator on GB300 — fp16 mma.sync GEMMs + flash-fused attention
// (constant-shift softmax; E never materialized).
// ---------------------------------------------------------------------------

#define NPIX 4096
#define BATCH 4
#define ESHIFT 4.0f

__device__ __half g_inT[BATCH * NPIX * 8];
__device__ __half g_a1 [BATCH * NPIX * 64];
__device__ __half g_a2 [BATCH * NPIX * 128];
__device__ __half g_a3 [BATCH * NPIX * 256];
__device__ __half g_qk [BATCH * NPIX * 128];          // [pix][2Cq]
__device__ __half g_v  [BATCH * 512 * NPIX];          // channel-major [c][pix]
__device__ __half g_t1 [BATCH * NPIX * 256];
__device__ __half g_t2 [BATCH * NPIX * 512];
__device__ __half g_a4 [BATCH * NPIX * 512];
__device__ float g_a3f[BATCH * NPIX * 256];
__device__ float g_a4f[BATCH * NPIX * 512];
__device__ float g_sig[8];
__device__ float g_qkb1[64];
__device__ float g_qkb2[128];
__device__ __half g_W1h[64 * 8];
__device__ __half g_W2h[128 * 64];
__device__ __half g_W3h[256 * 128];
__device__ __half g_W4h[512 * 256];
__device__ __half g_W5h[1 * 512];
__device__ __half g_qkW1h[64 * 256];
__device__ __half g_vW1h[256 * 256];
__device__ __half g_qkW2h[128 * 512];
__device__ __half g_vW2h[512 * 512];

__device__ __forceinline__ uint32_t smem_u32(const void* p) {
    uint32_t a;
    asm("{ .reg .u64 t; cvta.to.shared.u64 t, %1; cvt.u32.u64 %0, t; }" : "=r"(a) : "l"(p));
    return a;
}

#define LDMX4(r0, r1, r2, r3, ad) \
    asm volatile("ldmatrix.sync.aligned.m8n8.x4.shared.b16 {%0,%1,%2,%3}, [%4];\n" \
        : "=r"(r0), "=r"(r1), "=r"(r2), "=r"(r3) : "r"(ad))

#define MMA16816(d, a, b0, b1) \
    asm volatile("mma.sync.aligned.m16n8k16.row.col.f32.f16.f16.f32 " \
        "{%0,%1,%2,%3}, {%4,%5,%6,%7}, {%8,%9}, {%0,%1,%2,%3};\n" \
        : "+f"((d)[0]), "+f"((d)[1]), "+f"((d)[2]), "+f"((d)[3]) \
        : "r"((a)[0]), "r"((a)[1]), "r"((a)[2]), "r"((a)[3]), "r"(b0), "r"(b1))

// cp.async one 128-row x 64-half tile into SW128 smem (128B rows)
__device__ __forceinline__ void cpa_tile(uint32_t dstBase, const __half* src, int ld,
                                         int Rall, int r0, int K, int k0, int tid) {
    #pragma unroll
    for (int i = 0; i < 4; i++) {
        int e = tid + i * 256;
        int r = e >> 3, c = e & 7;
        int gr = r0 + r;
        uint32_t dst = dstBase + r * 128 + ((c ^ (r & 7)) << 4);
        bool ok = (gr < Rall) && (k0 + c * 8 < K);
        const __half* g = src + (ok ? ((size_t)gr * ld + k0 + c * 8) : 0);
        int bytes = ok ? 16 : 0;
        asm volatile("cp.async.cg.shared.global [%0], [%1], 16, %2;\n"
                     :: "r"(dst), "l"(g), "r"(bytes));
    }
}

// ---------------------------------------------------------------------------
// fp16 GEMM (convs): C[m][n] = sum_k A[m,k]*B[n,k]. x = n-tile (fast).
// EPI: 0 leaky(acc+bias[n]) -> fp16 (+f32 if WF32); 1 acc+bias[n] -> fp16;
//      4 acc+bias[n] -> fp16 transposed via smem bounce; 5 leaky -> f32.
// ---------------------------------------------------------------------------
template<int EPI, int WF32>
__global__ void __launch_bounds__(256, 2)
hgemm(const __half* __restrict__ A, const __half* __restrict__ B,
      __half* __restrict__ Ch, float* __restrict__ Cf,
      int Mall, int Nall, int K, int lda, int ldb, int ldc,
      size_t sA, size_t sB, size_t sC, size_t sCf,
      const float* __restrict__ bias)
{
    extern __shared__ char smem[];
    uint32_t sbase = smem_u32(smem);
    const uint32_t stageSz = 32768;

    int tid = threadIdx.x, lane = tid & 31, wid = tid >> 5;
    int bz = blockIdx.z;
    A += sA * bz;  B += sB * bz;

    int m0 = blockIdx.y * 128;
    int n0 = blockIdx.x * 128;
    int wm = (wid & 3) * 32;
    int wn = (wid >> 2) * 64;

    float acc[2][8][4];
    #pragma unroll
    for (int a = 0; a < 2; a++)
        #pragma unroll
        for (int b = 0; b < 8; b++)
            #pragma unroll
            for (int c = 0; c < 4; c++) acc[a][b][c] = 0.f;

    int nkt = (K + 63) >> 6;

    #pragma unroll
    for (int s = 0; s < 2; s++) {
        if (s < nkt) {
            uint32_t b = sbase + s * stageSz;
            cpa_tile(b, A, lda, Mall, m0, K, s * 64, tid);
            cpa_tile(b + 16384, B, ldb, Nall, n0, K, s * 64, tid);
        }
        asm volatile("cp.async.commit_group;\n");
    }

    for (int kt = 0; kt < nkt; kt++) {
        asm volatile("cp.async.wait_group 1;\n");
        __syncthreads();

        uint32_t Ab = sbase + (kt % 3) * stageSz;
        uint32_t Bb = Ab + 16384;

        int kl = K - kt * 64;
        int nks = (kl >= 64) ? 4 : ((kl + 15) >> 4);

        #pragma unroll 4
        for (int ks = 0; ks < nks; ks++) {
            int c0 = ks * 2;
            uint32_t af[2][4];
            #pragma unroll
            for (int mt = 0; mt < 2; mt++) {
                int lr = wm + mt * 16 + (lane & 15);
                int lc = c0 + (lane >> 4);
                LDMX4(af[mt][0], af[mt][1], af[mt][2], af[mt][3],
                      Ab + lr * 128 + ((lc ^ (lr & 7)) << 4));
            }
            uint32_t bf[8][2];
            #pragma unroll
            for (int j = 0; j < 4; j++) {
                int nb_ = wn + j * 16;
                int lr = nb_ + (lane & 7) + ((lane >> 4) << 3);
                int lc = c0 + ((lane >> 3) & 1);
                LDMX4(bf[2*j][0], bf[2*j][1], bf[2*j+1][0], bf[2*j+1][1],
                      Bb + lr * 128 + ((lc ^ (lr & 7)) << 4));
            }
            #pragma unroll
            for (int mt = 0; mt < 2; mt++)
                #pragma unroll
                for (int nt = 0; nt < 8; nt++)
                    MMA16816(acc[mt][nt], af[mt], bf[nt][0], bf[nt][1]);
        }

        int nx = kt + 2;
        if (nx < nkt) {
            uint32_t b = sbase + (nx % 3) * stageSz;
            cpa_tile(b, A, lda, Mall, m0, K, nx * 64, tid);
            cpa_tile(b + 16384, B, ldb, Nall, n0, K, nx * 64, tid);
        }
        asm volatile("cp.async.commit_group;\n");
    }

    __half* Cp = Ch + sC * bz;
    float*  Cfp = Cf + sCf * bz;
    int g = lane >> 2, tg = lane & 3;

    if (EPI == 4) {
        asm volatile("cp.async.wait_group 0;\n");
        __syncthreads();
        float* st = (float*)smem;
        #pragma unroll
        for (int mt = 0; mt < 2; mt++)
        #pragma unroll
        for (int h = 0; h < 2; h++) {
            int rl = wm + mt * 16 + g + h * 8;
            #pragma unroll
            for (int nt = 0; nt < 8; nt++) {
                int cl = wn + nt * 8 + tg * 2;
                st[cl * 132 + rl]       = acc[mt][nt][h * 2 + 0] + bias[n0 + cl];
                st[(cl + 1) * 132 + rl] = acc[mt][nt][h * 2 + 1] + bias[n0 + cl + 1];
            }
        }
        __syncthreads();
        int c = tid >> 1, ch = tid & 1;
        uint4 hb[8];
        __half* hbh = (__half*)hb;
        const float* sp = st + c * 132 + ch * 64;
        #pragma unroll
        for (int j = 0; j < 32; j++)
            ((__half2*)hbh)[j] = __floats2half2_rn(sp[2 * j], sp[2 * j + 1]);
        uint4* dp = (uint4*)&Cp[(size_t)(n0 + c) * NPIX + m0 + ch * 64];
        #pragma unroll
        for (int jj = 0; jj < 8; jj++) dp[jj] = hb[jj];
        return;
    }

    #pragma unroll
    for (int mt = 0; mt < 2; mt++)
    #pragma unroll
    for (int h = 0; h < 2; h++) {
        int row = m0 + wm + mt * 16 + g + h * 8;
        #pragma unroll
        for (int nt = 0; nt < 8; nt++) {
            int col = n0 + wn + nt * 8 + tg * 2;
            float v0 = acc[mt][nt][h * 2 + 0];
            float v1 = acc[mt][nt][h * 2 + 1];
            if (EPI == 0 || EPI == 5) {
                if (col < Nall)     { v0 += bias[col];     v0 = v0 > 0.f ? v0 : 0.1f * v0; }
                if (col + 1 < Nall) { v1 += bias[col + 1]; v1 = v1 > 0.f ? v1 : 0.1f * v1; }
            } else if (EPI == 1) {
                if (col < Nall)     v0 += bias[col];
                if (col + 1 < Nall) v1 += bias[col + 1];
            }
            if (EPI == 5) {
                if (col < Nall)     Cfp[(size_t)row * ldc + col]     = v0;
                if (col + 1 < Nall) Cfp[(size_t)row * ldc + col + 1] = v1;
            } else {
                if (col < Nall) {
                    *(__half2*)&Cp[(size_t)row * ldc + col] = __floats2half2_rn(v0, v1);
                    if (WF32)
                        *(float2*)&Cfp[(size_t)row * ldc + col] = make_float2(v0, v1);
                }
            }
        }
    }
}

// ---------------------------------------------------------------------------
// Flash attention: out[p][c] = gamma*(sum_n exp(S-4)*V[c][n])/(sum_n exp(S-4))
//                              + Res[p][c]
// CTA: 512 thr (16 warps), m-tile 128 queries, 256-channel chunk.
// grid = (Ctot/256, 32, BATCH). CQ = 32 or 64.
// smem: q 16K | P 32K | 2 stages x (k 16K + v 64K) | rbuf 2K | rinv 0.5K
// ---------------------------------------------------------------------------
#define FSQ 0u
#define FSP 16384u
#define FST 49152u
#define FSTG 81920u
#define FVO 16384u
#define FRB 212992u
#define FRI (FRB + 2048u)
#define FSMEM (FRI + 512u)

template<int CQ>
__global__ void __launch_bounds__(512, 1)
flash(const __half* __restrict__ QK, const __half* __restrict__ V,
      const float* __restrict__ Res, __half* __restrict__ Out,
      const float* __restrict__ gammaP, int Ctot)
{
    extern __shared__ char smem[];
    uint32_t sb = smem_u32(smem);
    int tid = threadIdx.x, lane = tid & 31, wid = tid >> 5;
    int g = lane >> 2, tg = lane & 3;
    int chunk = blockIdx.x, m0 = blockIdx.y * 128, bz = blockIdx.z;
    const int ldqk = 2 * CQ;

    const __half* qkB = QK + (size_t)bz * NPIX * ldqk;
    const __half* vB  = V + (size_t)bz * Ctot * NPIX + (size_t)(chunk * 256) * NPIX;

    // q tile: 128 x 64 halfs (zero-padded beyond CQ)
    #pragma unroll
    for (int i = tid; i < 1024; i += 512) {
        int r = i >> 3, u = i & 7;
        uint32_t dst = sb + FSQ + r * 128 + ((u ^ (r & 7)) << 4);
        int ok = (u * 8 < CQ) ? 16 : 0;
        const __half* gp = qkB + (size_t)(m0 + r) * ldqk + u * 8;
        asm volatile("cp.async.cg.shared.global [%0], [%1], 16, %2;\n"
                     :: "r"(dst), "l"(gp), "r"(ok));
    }

    int wmS = (wid & 3) * 32, wnS = (wid >> 2) * 32;
    int wn2 = (wid >> 2) * 64;

    // stage 0
    {
        uint32_t kb = sb + FST;
        #pragma unroll
        for (int i = tid; i < 1024; i += 512) {
            int r = i >> 3, u = i & 7;
            uint32_t dst = kb + r * 128 + ((u ^ (r & 7)) << 4);
            int ok = (u * 8 < CQ) ? 16 : 0;
            const __half* gp = qkB + (size_t)r * ldqk + CQ + u * 8;
            asm volatile("cp.async.cg.shared.global [%0], [%1], 16, %2;\n"
                         :: "r"(dst), "l"(gp), "r"(ok));
        }
        uint32_t vb = kb + FVO;
        #pragma unroll
        for (int i = tid; i < 4096; i += 512) {
            int r = i >> 4, u = i & 15;
            uint32_t dst = vb + r * 256 + ((u ^ (r & 7)) << 4);
            const __half* gp = vB + (size_t)r * NPIX + u * 8;
            asm volatile("cp.async.cg.shared.global [%0], [%1], 16;\n"
                         :: "r"(dst), "l"(gp));
        }
    }
    asm volatile("cp.async.commit_group;\n");

    float acc2[2][8][4];
    #pragma unroll
    for (int a = 0; a < 2; a++)
        #pragma unroll
        for (int b = 0; b < 8; b++)
            #pragma unroll
            for (int c = 0; c < 4; c++) acc2[a][b][c] = 0.f;
    float rsum[4] = {0.f, 0.f, 0.f, 0.f};

    for (int n = 0; n < 32; n++) {
        asm volatile("cp.async.wait_group 0;\n");
        __syncthreads();
        int buf = n & 1;

        // prefetch stage n+1
        if (n + 1 < 32) {
            uint32_t kb = sb + FST + (buf ^ 1) * FSTG;
            int n0 = (n + 1) * 128;
            #pragma unroll
            for (int i = tid; i < 1024; i += 512) {
                int r = i >> 3, u = i & 7;
                uint32_t dst = kb + r * 128 + ((u ^ (r & 7)) << 4);
                int ok = (u * 8 < CQ) ? 16 : 0;
                const __half* gp = qkB + (size_t)(n0 + r) * ldqk + CQ + u * 8;
                asm volatile("cp.async.cg.shared.global [%0], [%1], 16, %2;\n"
                             :: "r"(dst), "l"(gp), "r"(ok));
            }
            uint32_t vb = kb + FVO;
            #pragma unroll
            for (int i = tid; i < 4096; i += 512) {
                int r = i >> 4, u = i & 15;
                uint32_t dst = vb + r * 256 + ((u ^ (r & 7)) << 4);
                const __half* gp = vB + (size_t)r * NPIX + n0 + u * 8;
                asm volatile("cp.async.cg.shared.global [%0], [%1], 16;\n"
                             :: "r"(dst), "l"(gp));
            }
        }
        asm volatile("cp.async.commit_group;\n");

        uint32_t kb = sb + FST + buf * FSTG;
        uint32_t vb = kb + FVO;

        // ---- S = q . k^T  (per mt to limit registers), exp, P store
        #pragma unroll
        for (int mt = 0; mt < 2; mt++) {
            float sa[4][4];
            #pragma unroll
            for (int a = 0; a < 4; a++)
                #pragma unroll
                for (int c = 0; c < 4; c++) sa[a][c] = 0.f;

            #pragma unroll
            for (int ks = 0; ks < CQ / 16; ks++) {
                int c0 = ks * 2;
                uint32_t af[4];
                {
                    int lr = wmS + mt * 16 + (lane & 15);
                    int lc = c0 + (lane >> 4);
                    LDMX4(af[0], af[1], af[2], af[3],
                          sb + FSQ + lr * 128 + ((lc ^ (lr & 7)) << 4));
                }
                uint32_t bf[4][2];
                #pragma unroll
                for (int j = 0; j < 2; j++) {
                    int nb_ = wnS + j * 16;
                    int lr = nb_ + (lane & 7) + ((lane >> 4) << 3);
                    int lc = c0 + ((lane >> 3) & 1);
                    LDMX4(bf[2*j][0], bf[2*j][1], bf[2*j+1][0], bf[2*j+1][1],
                          kb + lr * 128 + ((lc ^ (lr & 7)) << 4));
                }
                #pragma unroll
                for (int nt = 0; nt < 4; nt++)
                    MMA16816(sa[nt], af, bf[nt][0], bf[nt][1]);
            }

            #pragma unroll
            for (int h = 0; h < 2; h++) {
                int rl = wmS + mt * 16 + g + h * 8;
                #pragma unroll
                for (int nt = 0; nt < 4; nt++) {
                    float e0 = __expf(sa[nt][h * 2 + 0] - ESHIFT);
                    float e1 = __expf(sa[nt][h * 2 + 1] - ESHIFT);
                    rsum[mt * 2 + h] += e0 + e1;
                    int u = (wnS >> 3) + nt;
                    *(__half2*)(smem + FSP + rl * 256 + ((u ^ (rl & 7)) << 4) + tg * 4)
                        = __floats2half2_rn(e0, e1);
                }
            }
        }
        __syncthreads();

        // ---- PV: acc2 += P . V^T   (K = 128 over n)
        #pragma unroll
        for (int ks = 0; ks < 8; ks++) {
            int c0 = ks * 2;
            uint32_t af2[2][4];
            #pragma unroll
            for (int mt = 0; mt < 2; mt++) {
                int lr = wmS + mt * 16 + (lane & 15);
                int lc = c0 + (lane >> 4);
                LDMX4(af2[mt][0], af2[mt][1], af2[mt][2], af2[mt][3],
                      sb + FSP + lr * 256 + ((lc ^ (lr & 7)) << 4));
            }
            uint32_t bf2[8][2];
            #pragma unroll
            for (int j = 0; j < 4; j++) {
                int nb_ = wn2 + j * 16;
                int lr = nb_ + (lane & 7) + ((lane >> 4) << 3);
                int lc = c0 + ((lane >> 3) & 1);
                LDMX4(bf2[2*j][0], bf2[2*j][1], bf2[2*j+1][0], bf2[2*j+1][1],
                      vb + lr * 256 + ((lc ^ (lr & 7)) << 4));
            }
            #pragma unroll
            for (int mt = 0; mt < 2; mt++)
                #pragma unroll
                for (int nt = 0; nt < 8; nt++)
                    MMA16816(acc2[mt][nt], af2[mt], bf2[nt][0], bf2[nt][1]);
        }
        __syncthreads();
    }

    // ---- rowsum reduction (fixed order, deterministic)
    #pragma unroll
    for (int i = 0; i < 4; i++) {
        rsum[i] += __shfl_xor_sync(0xffffffffu, rsum[i], 1);
        rsum[i] += __shfl_xor_sync(0xffffffffu, rsum[i], 2);
    }
    float* rbuf = (float*)(smem + FRB);
    if (tg == 0) {
        #pragma unroll
        for (int mt = 0; mt < 2; mt++)
            #pragma unroll
            for (int h = 0; h < 2; h++)
                rbuf[(wid >> 2) * 128 + wmS + mt * 16 + g + h * 8] = rsum[mt * 2 + h];
    }
    __syncthreads();
    float* rinv = (float*)(smem + FRI);
    if (tid < 128) {
        float s = rbuf[tid] + rbuf[128 + tid] + rbuf[256 + tid] + rbuf[384 + tid];
        rinv[tid] = 1.f / s;
    }
    __syncthreads();

    float gam = *gammaP;
    const float* RB_ = Res + ((size_t)bz * NPIX + m0) * Ctot + chunk * 256;
    __half* OB = Out + ((size_t)bz * NPIX + m0) * Ctot + chunk * 256;
    #pragma unroll
    for (int mt = 0; mt < 2; mt++)
    #pragma unroll
    for (int h = 0; h < 2; h++) {
        int rl = wmS + mt * 16 + g + h * 8;
        float is = gam * rinv[rl];
        #pragma unroll
        for (int nt = 0; nt < 8; nt++) {
            int cl = wn2 + nt * 8 + tg * 2;
            const float* rp = RB_ + (size_t)rl * Ctot + cl;
            float v0 = acc2[mt][nt][h * 2 + 0] * is + rp[0];
            float v1 = acc2[mt][nt][h * 2 + 1] * is + rp[1];
            *(__half2*)&OB[(size_t)rl * Ctot + cl] = __floats2half2_rn(v0, v1);
        }
    }
}

// ---------------------------------------------------------------------------
// spectral norms (all 5, one block each)
// ---------------------------------------------------------------------------
__global__ void snorm_all(const float* __restrict__ W1, const float* __restrict__ u1,
                          const float* __restrict__ W2, const float* __restrict__ u2,
                          const float* __restrict__ W3, const float* __restrict__ u3,
                          const float* __restrict__ W4, const float* __restrict__ u4,
                          const float* __restrict__ W5, const float* __restrict__ u5,
                          float* __restrict__ sig)
{
    __shared__ float vs[512];
    __shared__ float us[512];
    __shared__ float red[256];
    __shared__ float red8[8];

    const float* W; const float* u; int O, C;
    switch (blockIdx.x) {
        case 0: W = W1; u = u1; O = 64;  C = 6;   break;
        case 1: W = W2; u = u2; O = 128; C = 64;  break;
        case 2: W = W3; u = u3; O = 256; C = 128; break;
        case 3: W = W4; u = u4; O = 512; C = 256; break;
        default: W = W5; u = u5; O = 1;  C = 512; break;
    }
    int t = threadIdx.x, lane = t & 31, wid = t >> 5;

    for (int o = t; o < O; o += 256) us[o] = u[o];
    __syncthreads();
    for (int c = t; c < C; c += 256) {
        float s = 0.f;
        #pragma unroll 4
        for (int o = 0; o < O; o++) s += W[(size_t)o * C + c] * us[o];
        vs[c] = s;
    }
    __syncthreads();
    float s = 0.f;
    for (int c = t; c < C; c += 256) s += vs[c] * vs[c];
    red[t] = s; __syncthreads();
    for (int off = 128; off > 0; off >>= 1) { if (t < off) red[t] += red[t + off]; __syncthreads(); }
    float vinv = 1.f / (sqrtf(red[0]) + 1e-12f);
    __syncthreads();
    for (int c = t; c < C; c += 256) vs[c] *= vinv;
    __syncthreads();
    float accq = 0.f;
    for (int o = wid; o < O; o += 8) {
        float tv = 0.f;
        for (int c = lane; c < C; c += 32) tv += W[(size_t)o * C + c] * vs[c];
        #pragma unroll
        for (int off = 16; off > 0; off >>= 1) tv += __shfl_xor_sync(0xffffffffu, tv, off);
        if (lane == 0) accq += tv * tv;
    }
    if (lane == 0) red8[wid] = accq;
    __syncthreads();
    if (t == 0) {
        float S = 0.f;
        #pragma unroll
        for (int w = 0; w < 8; w++) S += red8[w];
        float sigma = S / (sqrtf(S) + 1e-12f);
        sig[blockIdx.x] = 1.f / sigma;
    }
}

// ---------------------------------------------------------------------------
// weight conversion f32 -> fp16 (scaled for W1..W5), K zero-padded, q|k concat
// ---------------------------------------------------------------------------
__global__ void wprep(const float* W1, const float* W2, const float* W3,
                      const float* W4, const float* W5,
                      const float* q1, const float* k1, const float* v1,
                      const float* q2, const float* k2, const float* v2,
                      const float* sig,
                      __half* o0, __half* o1, __half* o2, __half* o3, __half* o4,
                      __half* qk1, __half* vv1, __half* qk2, __half* vv2)
{
    const float* src; __half* dst; int O, C, Cp; float s = 1.f;
    switch (blockIdx.x) {
        case 0:  src = W1; dst = o0;             O = 64;  C = 6;   Cp = 8;   s = sig[0]; break;
        case 1:  src = W2; dst = o1;             O = 128; C = 64;  Cp = 64;  s = sig[1]; break;
        case 2:  src = W3; dst = o2;             O = 256; C = 128; Cp = 128; s = sig[2]; break;
        case 3:  src = W4; dst = o3;             O = 512; C = 256; Cp = 256; s = sig[3]; break;
        case 4:  src = W5; dst = o4;             O = 1;   C = 512; Cp = 512; s = sig[4]; break;
        case 5:  src = q1; dst = qk1;            O = 32;  C = 256; Cp = 256; break;
        case 6:  src = k1; dst = qk1 + 32 * 256; O = 32;  C = 256; Cp = 256; break;
        case 7:  src = v1; dst = vv1;            O = 256; C = 256; Cp = 256; break;
        case 8:  src = q2; dst = qk2;            O = 64;  C = 512; Cp = 512; break;
        case 9:  src = k2; dst = qk2 + 64 * 512; O = 64;  C = 512; Cp = 512; break;
        default: src = v2; dst = vv2;            O = 512; C = 512; Cp = 512; break;
    }
    int total = O * Cp;
    for (int i = blockIdx.y * 256 + threadIdx.x; i < total; i += 8 * 256) {
        int o = i / Cp, c = i % Cp;
        float v = (c < C) ? src[(size_t)o * C + c] * s : 0.f;
        dst[i] = __float2half(v);
    }
}

__global__ void biascat(const float* qb1, const float* kb1,
                        const float* qb2, const float* kb2,
                        float* d1, float* d2) {
    int t = threadIdx.x;
    if (t < 32) d1[t] = qb1[t];
    else if (t < 64) d1[t] = kb1[t - 32];
    if (t < 64) d2[t] = qb2[t];
    else d2[t] = kb2[t - 64];
}

__global__ void tin(const float* __restrict__ in, __half* __restrict__ out) {
    int b = blockIdx.y;
    int p = blockIdx.x * 256 + threadIdx.x;
    const float* s = in + (size_t)b * 6 * NPIX + p;
    __half h[8];
    #pragma unroll
    for (int c = 0; c < 6; c++) h[c] = __float2half(s[(size_t)c * NPIX]);
    h[6] = __float2half(0.f);
    h[7] = __float2half(0.f);
    *(uint4*)(out + ((size_t)b * NPIX + p) * 8) = *(uint4*)h;
}

// ---------------------------------------------------------------------------
// kernel_launch
// ---------------------------------------------------------------------------
extern "C" void kernel_launch(void* const* d_in, const int* in_sizes, int n_in,
                              void* d_out, int out_size)
{
    const float* inp  = (const float*)d_in[0];
    const float* W1 = (const float*)d_in[1];  const float* b1 = (const float*)d_in[2];  const float* u1 = (const float*)d_in[3];
    const float* W2 = (const float*)d_in[4];  const float* b2 = (const float*)d_in[5];  const float* u2 = (const float*)d_in[6];
    const float* W3 = (const float*)d_in[7];  const float* b3 = (const float*)d_in[8];  const float* u3 = (const float*)d_in[9];
    const float* W4 = (const float*)d_in[10]; const float* b4 = (const float*)d_in[11]; const float* u4 = (const float*)d_in[12];
    const float* W5 = (const float*)d_in[13]; const float* b5 = (const float*)d_in[14]; const float* u5 = (const float*)d_in[15];
    const float* a1qW = (const float*)d_in[16]; const float* a1qb = (const float*)d_in[17];
    const float* a1kW = (const float*)d_in[18]; const float* a1kb = (const float*)d_in[19];
    const float* a1vW = (const float*)d_in[20]; const float* a1vb = (const float*)d_in[21];
    const float* a1g  = (const float*)d_in[22];
    const float* a2qW = (const float*)d_in[23]; const float* a2qb = (const float*)d_in[24];
    const float* a2kW = (const float*)d_in[25]; const float* a2kb = (const float*)d_in[26];
    const float* a2vW = (const float*)d_in[27]; const float* a2vb = (const float*)d_in[28];
    const float* a2g  = (const float*)d_in[29];

    __half *inTh, *a1h, *a2h, *a3h, *qkh, *vh, *t1h, *t2h, *a4h;
    __half *W1h, *W2h, *W3h, *W4h, *W5h, *qkW1h, *vW1h, *qkW2h, *vW2h;
    float *a3f, *a4f, *sig, *qkb1, *qkb2;
    cudaGetSymbolAddress((void**)&inTh, g_inT);
    cudaGetSymbolAddress((void**)&a1h, g_a1);
    cudaGetSymbolAddress((void**)&a2h, g_a2);
    cudaGetSymbolAddress((void**)&a3h, g_a3);
    cudaGetSymbolAddress((void**)&qkh, g_qk);
    cudaGetSymbolAddress((void**)&vh,  g_v);
    cudaGetSymbolAddress((void**)&t1h, g_t1);
    cudaGetSymbolAddress((void**)&t2h, g_t2);
    cudaGetSymbolAddress((void**)&a4h, g_a4);
    cudaGetSymbolAddress((void**)&a3f, g_a3f);
    cudaGetSymbolAddress((void**)&a4f, g_a4f);
    cudaGetSymbolAddress((void**)&sig, g_sig);
    cudaGetSymbolAddress((void**)&qkb1, g_qkb1);
    cudaGetSymbolAddress((void**)&qkb2, g_qkb2);
    cudaGetSymbolAddress((void**)&W1h, g_W1h);
    cudaGetSymbolAddress((void**)&W2h, g_W2h);
    cudaGetSymbolAddress((void**)&W3h, g_W3h);
    cudaGetSymbolAddress((void**)&W4h, g_W4h);
    cudaGetSymbolAddress((void**)&W5h, g_W5h);
    cudaGetSymbolAddress((void**)&qkW1h, g_qkW1h);
    cudaGetSymbolAddress((void**)&vW1h, g_vW1h);
    cudaGetSymbolAddress((void**)&qkW2h, g_qkW2h);
    cudaGetSymbolAddress((void**)&vW2h, g_vW2h);

    const int SMEMSZ = 98304;
    cudaFuncSetAttribute(hgemm<0,0>, cudaFuncAttributeMaxDynamicSharedMemorySize, SMEMSZ);
    cudaFuncSetAttribute(hgemm<0,1>, cudaFuncAttributeMaxDynamicSharedMemorySize, SMEMSZ);
    cudaFuncSetAttribute(hgemm<1,0>, cudaFuncAttributeMaxDynamicSharedMemorySize, SMEMSZ);
    cudaFuncSetAttribute(hgemm<4,0>, cudaFuncAttributeMaxDynamicSharedMemorySize, SMEMSZ);
    cudaFuncSetAttribute(hgemm<5,0>, cudaFuncAttributeMaxDynamicSharedMemorySize, SMEMSZ);
    cudaFuncSetAttribute(flash<32>, cudaFuncAttributeMaxDynamicSharedMemorySize, FSMEM);
    cudaFuncSetAttribute(flash<64>, cudaFuncAttributeMaxDynamicSharedMemorySize, FSMEM);

    const size_t NP = NPIX;
    auto gd = [&](int Nn) { return dim3((Nn + 127) / 128, NPIX / 128, BATCH); };

    snorm_all<<<5, 256>>>(W1, u1, W2, u2, W3, u3, W4, u4, W5, u5, sig);
    wprep<<<dim3(11, 8), 256>>>(W1, W2, W3, W4, W5, a1qW, a1kW, a1vW, a2qW, a2kW, a2vW,
                                sig, W1h, W2h, W3h, W4h, W5h, qkW1h, vW1h, qkW2h, vW2h);
    biascat<<<1, 128>>>(a1qb, a1kb, a2qb, a2kb, qkb1, qkb2);
    tin<<<dim3(16, BATCH), 256>>>(inp, inTh);

    // conv1/2/3
    hgemm<0,0><<<gd(64), 256, SMEMSZ>>>(inTh, W1h, a1h, nullptr, NPIX, 64, 8, 8, 8, 64,
        NP * 8, 0, NP * 64, 0, b1);
    hgemm<0,0><<<gd(128), 256, SMEMSZ>>>(a1h, W2h, a2h, nullptr, NPIX, 128, 64, 64, 64, 128,
        NP * 64, 0, NP * 128, 0, b2);
    hgemm<0,1><<<gd(256), 256, SMEMSZ>>>(a2h, W3h, a3h, a3f, NPIX, 256, 128, 128, 128, 256,
        NP * 128, 0, NP * 256, NP * 256, b3);

    // attention 1 (C=256, Cq=32)
    hgemm<1,0><<<gd(64), 256, SMEMSZ>>>(a3h, qkW1h, qkh, nullptr, NPIX, 64, 256, 256, 256, 64,
        NP * 256, 0, NP * 64, 0, qkb1);
    hgemm<4,0><<<gd(256), 256, SMEMSZ>>>(a3h, vW1h, vh, nullptr, NPIX, 256, 256, 256, 256, NPIX,
        NP * 256, 0, 256 * NP, 0, a1vb);
    flash<32><<<dim3(1, 32, BATCH), 512, FSMEM>>>(qkh, vh, a3f, t1h, a1g, 256);

    // conv4
    hgemm<0,1><<<gd(512), 256, SMEMSZ>>>(t1h, W4h, a4h, a4f, NPIX, 512, 256, 256, 256, 512,
        NP * 256, 0, NP * 512, NP * 512, b4);

    // attention 2 (C=512, Cq=64)
    hgemm<1,0><<<gd(128), 256, SMEMSZ>>>(a4h, qkW2h, qkh, nullptr, NPIX, 128, 512, 512, 512, 128,
        NP * 512, 0, NP * 128, 0, qkb2);
    hgemm<4,0><<<gd(512), 256, SMEMSZ>>>(a4h, vW2h, vh, nullptr, NPIX, 512, 512, 512, 512, NPIX,
        NP * 512, 0, 512 * NP, 0, a2vb);
    flash<64><<<dim3(2, 32, BATCH), 512, FSMEM>>>(qkh, vh, a4f, t2h, a2g, 512);

    // conv5 -> f32 output (B, 4096)
    hgemm<5,0><<<gd(1), 256, SMEMSZ>>>(t2h, W5h, nullptr, (float*)d_out, NPIX, 1, 512, 512, 512, 1,
        NP * 512, 0, 0, NP, b5);
}

// round 11
// speedup vs baseline: 1.2606x; 1.0524x over previous
#include <cuda_runtime.h>
#include <cuda_fp16.h>
#include <math.h>
#include <stdint.h>

// ---------------------------------------------------------------------------
// SpectralDiscriminator on GB300 — fp16 mma.sync GEMMs + flash-fused attention.
// R11: fp16 residuals (no f32 copies), merged q|k|v conv, fewer launches.
// ---------------------------------------------------------------------------

#define NPIX 4096
#define BATCH 4
#define ESHIFT 4.0f

__device__ __half g_inT[BATCH * NPIX * 8];
__device__ __half g_a1 [BATCH * NPIX * 64];
__device__ __half g_a2 [BATCH * NPIX * 128];
__device__ __half g_a3 [BATCH * NPIX * 256];
__device__ __half g_qk [BATCH * NPIX * 128];          // [pix][128]: q|k (+pad for attn1)
__device__ __half g_v  [BATCH * 512 * NPIX];          // channel-major [c][pix]
__device__ __half g_t1 [BATCH * NPIX * 256];
__device__ __half g_t2 [BATCH * NPIX * 512];
__device__ __half g_a4 [BATCH * NPIX * 512];
__device__ float g_sig[8];
__device__ float g_qkb1[128];
__device__ float g_qkb2[128];
__device__ __half g_W1h[64 * 8];
__device__ __half g_W2h[128 * 64];
__device__ __half g_W3h[256 * 128];
__device__ __half g_W4h[512 * 256];
__device__ __half g_W5h[1 * 512];
__device__ __half g_qkv1h[384 * 256];   // [q32|k32|pad64|v256] x 256
__device__ __half g_qkv2h[640 * 512];   // [q64|k64|v512] x 512

__device__ __forceinline__ uint32_t smem_u32(const void* p) {
    uint32_t a;
    asm("{ .reg .u64 t; cvta.to.shared.u64 t, %1; cvt.u32.u64 %0, t; }" : "=r"(a) : "l"(p));
    return a;
}

#define LDMX4(r0, r1, r2, r3, ad) \
    asm volatile("ldmatrix.sync.aligned.m8n8.x4.shared.b16 {%0,%1,%2,%3}, [%4];\n" \
        : "=r"(r0), "=r"(r1), "=r"(r2), "=r"(r3) : "r"(ad))

#define MMA16816(d, a, b0, b1) \
    asm volatile("mma.sync.aligned.m16n8k16.row.col.f32.f16.f16.f32 " \
        "{%0,%1,%2,%3}, {%4,%5,%6,%7}, {%8,%9}, {%0,%1,%2,%3};\n" \
        : "+f"((d)[0]), "+f"((d)[1]), "+f"((d)[2]), "+f"((d)[3]) \
        : "r"((a)[0]), "r"((a)[1]), "r"((a)[2]), "r"((a)[3]), "r"(b0), "r"(b1))

// cp.async one 128-row x 64-half tile into SW128 smem (128B rows)
__device__ __forceinline__ void cpa_tile(uint32_t dstBase, const __half* src, int ld,
                                         int Rall, int r0, int K, int k0, int tid) {
    #pragma unroll
    for (int i = 0; i < 4; i++) {
        int e = tid + i * 256;
        int r = e >> 3, c = e & 7;
        int gr = r0 + r;
        uint32_t dst = dstBase + r * 128 + ((c ^ (r & 7)) << 4);
        bool ok = (gr < Rall) && (k0 + c * 8 < K);
        const __half* g = src + (ok ? ((size_t)gr * ld + k0 + c * 8) : 0);
        int bytes = ok ? 16 : 0;
        asm volatile("cp.async.cg.shared.global [%0], [%1], 16, %2;\n"
                     :: "r"(dst), "l"(g), "r"(bytes));
    }
}

// ---------------------------------------------------------------------------
// fp16 GEMM: C[m][n] = sum_k A[m,k]*B[n,k]. x = n-tile (fast), y = m-tile.
// EPI: 0 leaky(acc+bias[n]) -> fp16
//      5 leaky(acc+bias[n]) -> f32 (final layer)
//      7 merged qkv: blockIdx.x < qkTiles -> acc+bias[n] plain to Ch (ldc);
//                    else -> acc+vbias transposed to C2[(n-128)*NPIX+m] via bounce
// ---------------------------------------------------------------------------
template<int EPI>
__global__ void __launch_bounds__(256, 2)
hgemm(const __half* __restrict__ A, const __half* __restrict__ B,
      __half* __restrict__ Ch, __half* __restrict__ C2, float* __restrict__ Cf,
      int Mall, int Nall, int K, int lda, int ldb, int ldc,
      size_t sA, size_t sB, size_t sC, size_t sC2, int qkTiles,
      const float* __restrict__ bias, const float* __restrict__ vbias)
{
    extern __shared__ char smem[];
    uint32_t sbase = smem_u32(smem);
    const uint32_t stageSz = 32768;

    int tid = threadIdx.x, lane = tid & 31, wid = tid >> 5;
    int bz = blockIdx.z;
    A += sA * bz;  B += sB * bz;

    int m0 = blockIdx.y * 128;
    int n0 = blockIdx.x * 128;
    int wm = (wid & 3) * 32;
    int wn = (wid >> 2) * 64;

    float acc[2][8][4];
    #pragma unroll
    for (int a = 0; a < 2; a++)
        #pragma unroll
        for (int b = 0; b < 8; b++)
            #pragma unroll
            for (int c = 0; c < 4; c++) acc[a][b][c] = 0.f;

    int nkt = (K + 63) >> 6;

    #pragma unroll
    for (int s = 0; s < 2; s++) {
        if (s < nkt) {
            uint32_t b = sbase + s * stageSz;
            cpa_tile(b, A, lda, Mall, m0, K, s * 64, tid);
            cpa_tile(b + 16384, B, ldb, Nall, n0, K, s * 64, tid);
        }
        asm volatile("cp.async.commit_group;\n");
    }

    for (int kt = 0; kt < nkt; kt++) {
        asm volatile("cp.async.wait_group 1;\n");
        __syncthreads();

        uint32_t Ab = sbase + (kt % 3) * stageSz;
        uint32_t Bb = Ab + 16384;

        int kl = K - kt * 64;
        int nks = (kl >= 64) ? 4 : ((kl + 15) >> 4);

        #pragma unroll 4
        for (int ks = 0; ks < nks; ks++) {
            int c0 = ks * 2;
            uint32_t af[2][4];
            #pragma unroll
            for (int mt = 0; mt < 2; mt++) {
                int lr = wm + mt * 16 + (lane & 15);
                int lc = c0 + (lane >> 4);
                LDMX4(af[mt][0], af[mt][1], af[mt][2], af[mt][3],
                      Ab + lr * 128 + ((lc ^ (lr & 7)) << 4));
            }
            uint32_t bf[8][2];
            #pragma unroll
            for (int j = 0; j < 4; j++) {
                int nb_ = wn + j * 16;
                int lr = nb_ + (lane & 7) + ((lane >> 4) << 3);
                int lc = c0 + ((lane >> 3) & 1);
                LDMX4(bf[2*j][0], bf[2*j][1], bf[2*j+1][0], bf[2*j+1][1],
                      Bb + lr * 128 + ((lc ^ (lr & 7)) << 4));
            }
            #pragma unroll
            for (int mt = 0; mt < 2; mt++)
                #pragma unroll
                for (int nt = 0; nt < 8; nt++)
                    MMA16816(acc[mt][nt], af[mt], bf[nt][0], bf[nt][1]);
        }

        int nx = kt + 2;
        if (nx < nkt) {
            uint32_t b = sbase + (nx % 3) * stageSz;
            cpa_tile(b, A, lda, Mall, m0, K, nx * 64, tid);
            cpa_tile(b + 16384, B, ldb, Nall, n0, K, nx * 64, tid);
        }
        asm volatile("cp.async.commit_group;\n");
    }

    int g = lane >> 2, tg = lane & 3;

    if (EPI == 7) {
        if ((int)blockIdx.x < qkTiles) {
            // plain pixel-major store to qk buffer (128 cols, all exist)
            __half* Cp = Ch + sC * bz;
            #pragma unroll
            for (int mt = 0; mt < 2; mt++)
            #pragma unroll
            for (int h = 0; h < 2; h++) {
                int row = m0 + wm + mt * 16 + g + h * 8;
                #pragma unroll
                for (int nt = 0; nt < 8; nt++) {
                    int col = n0 + wn + nt * 8 + tg * 2;
                    float v0 = acc[mt][nt][h * 2 + 0] + bias[col];
                    float v1 = acc[mt][nt][h * 2 + 1] + bias[col + 1];
                    *(__half2*)&Cp[(size_t)row * ldc + col] = __floats2half2_rn(v0, v1);
                }
            }
        } else {
            // transposed store of v columns via smem bounce
            int vbase = n0 - qkTiles * 128;
            asm volatile("cp.async.wait_group 0;\n");
            __syncthreads();
            float* st = (float*)smem;
            #pragma unroll
            for (int mt = 0; mt < 2; mt++)
            #pragma unroll
            for (int h = 0; h < 2; h++) {
                int rl = wm + mt * 16 + g + h * 8;
                #pragma unroll
                for (int nt = 0; nt < 8; nt++) {
                    int cl = wn + nt * 8 + tg * 2;
                    st[cl * 132 + rl]       = acc[mt][nt][h * 2 + 0] + vbias[vbase + cl];
                    st[(cl + 1) * 132 + rl] = acc[mt][nt][h * 2 + 1] + vbias[vbase + cl + 1];
                }
            }
            __syncthreads();
            int c = tid >> 1, ch = tid & 1;
            uint4 hb[8];
            __half* hbh = (__half*)hb;
            const float* sp = st + c * 132 + ch * 64;
            #pragma unroll
            for (int j = 0; j < 32; j++)
                ((__half2*)hbh)[j] = __floats2half2_rn(sp[2 * j], sp[2 * j + 1]);
            uint4* dp = (uint4*)&C2[sC2 * bz + (size_t)(vbase + c) * NPIX + m0 + ch * 64];
            #pragma unroll
            for (int jj = 0; jj < 8; jj++) dp[jj] = hb[jj];
        }
        return;
    }

    __half* Cp = Ch + sC * bz;
    float*  Cfp = Cf + sC * bz;
    #pragma unroll
    for (int mt = 0; mt < 2; mt++)
    #pragma unroll
    for (int h = 0; h < 2; h++) {
        int row = m0 + wm + mt * 16 + g + h * 8;
        #pragma unroll
        for (int nt = 0; nt < 8; nt++) {
            int col = n0 + wn + nt * 8 + tg * 2;
            float v0 = acc[mt][nt][h * 2 + 0];
            float v1 = acc[mt][nt][h * 2 + 1];
            if (col < Nall)     { v0 += bias[col];     v0 = v0 > 0.f ? v0 : 0.1f * v0; }
            if (col + 1 < Nall) { v1 += bias[col + 1]; v1 = v1 > 0.f ? v1 : 0.1f * v1; }
            if (EPI == 5) {
                if (col < Nall)     Cfp[(size_t)row * ldc + col]     = v0;
                if (col + 1 < Nall) Cfp[(size_t)row * ldc + col + 1] = v1;
            } else {
                if (col < Nall)
                    *(__half2*)&Cp[(size_t)row * ldc + col] = __floats2half2_rn(v0, v1);
            }
        }
    }
}

// ---------------------------------------------------------------------------
// Flash attention: out[p][c] = gamma*(sum_n exp(S-4)*V[c][n])/(sum_n exp(S-4))
//                              + Res[p][c]   (Res fp16, pixel-major)
// CTA: 512 thr (16 warps), m-tile 128 queries, 256-channel chunk.
// qk layout: [pix][128] with q at cols [0,CQ), k at [CQ,2CQ).
// ---------------------------------------------------------------------------
#define FSQ 0u
#define FSP 16384u
#define FST 49152u
#define FSTG 81920u
#define FVO 16384u
#define FRB 212992u
#define FRI (FRB + 2048u)
#define FSMEM (FRI + 512u)

template<int CQ>
__global__ void __launch_bounds__(512, 1)
flash(const __half* __restrict__ QK, const __half* __restrict__ V,
      const __half* __restrict__ Res, __half* __restrict__ Out,
      const float* __restrict__ gammaP, int Ctot)
{
    extern __shared__ char smem[];
    uint32_t sb = smem_u32(smem);
    int tid = threadIdx.x, lane = tid & 31, wid = tid >> 5;
    int g = lane >> 2, tg = lane & 3;
    int chunk = blockIdx.x, m0 = blockIdx.y * 128, bz = blockIdx.z;
    const int ldqk = 128;

    const __half* qkB = QK + (size_t)bz * NPIX * ldqk;
    const __half* vB  = V + (size_t)bz * Ctot * NPIX + (size_t)(chunk * 256) * NPIX;

    #pragma unroll
    for (int i = tid; i < 1024; i += 512) {
        int r = i >> 3, u = i & 7;
        uint32_t dst = sb + FSQ + r * 128 + ((u ^ (r & 7)) << 4);
        int ok = (u * 8 < CQ) ? 16 : 0;
        const __half* gp = qkB + (size_t)(m0 + r) * ldqk + u * 8;
        asm volatile("cp.async.cg.shared.global [%0], [%1], 16, %2;\n"
                     :: "r"(dst), "l"(gp), "r"(ok));
    }

    int wmS = (wid & 3) * 32, wnS = (wid >> 2) * 32;
    int wn2 = (wid >> 2) * 64;

    {
        uint32_t kb = sb + FST;
        #pragma unroll
        for (int i = tid; i < 1024; i += 512) {
            int r = i >> 3, u = i & 7;
            uint32_t dst = kb + r * 128 + ((u ^ (r & 7)) << 4);
            int ok = (u * 8 < CQ) ? 16 : 0;
            const __half* gp = qkB + (size_t)r * ldqk + CQ + u * 8;
            asm volatile("cp.async.cg.shared.global [%0], [%1], 16, %2;\n"
                         :: "r"(dst), "l"(gp), "r"(ok));
        }
        uint32_t vb = kb + FVO;
        #pragma unroll
        for (int i = tid; i < 4096; i += 512) {
            int r = i >> 4, u = i & 15;
            uint32_t dst = vb + r * 256 + ((u ^ (r & 7)) << 4);
            const __half* gp = vB + (size_t)r * NPIX + u * 8;
            asm volatile("cp.async.cg.shared.global [%0], [%1], 16;\n"
                         :: "r"(dst), "l"(gp));
        }
    }
    asm volatile("cp.async.commit_group;\n");

    float acc2[2][8][4];
    #pragma unroll
    for (int a = 0; a < 2; a++)
        #pragma unroll
        for (int b = 0; b < 8; b++)
            #pragma unroll
            for (int c = 0; c < 4; c++) acc2[a][b][c] = 0.f;
    float rsum[4] = {0.f, 0.f, 0.f, 0.f};

    for (int n = 0; n < 32; n++) {
        asm volatile("cp.async.wait_group 0;\n");
        __syncthreads();
        int buf = n & 1;

        if (n + 1 < 32) {
            uint32_t kb = sb + FST + (buf ^ 1) * FSTG;
            int n0 = (n + 1) * 128;
            #pragma unroll
            for (int i = tid; i < 1024; i += 512) {
                int r = i >> 3, u = i & 7;
                uint32_t dst = kb + r * 128 + ((u ^ (r & 7)) << 4);
                int ok = (u * 8 < CQ) ? 16 : 0;
                const __half* gp = qkB + (size_t)(n0 + r) * ldqk + CQ + u * 8;
                asm volatile("cp.async.cg.shared.global [%0], [%1], 16, %2;\n"
                             :: "r"(dst), "l"(gp), "r"(ok));
            }
            uint32_t vb = kb + FVO;
            #pragma unroll
            for (int i = tid; i < 4096; i += 512) {
                int r = i >> 4, u = i & 15;
                uint32_t dst = vb + r * 256 + ((u ^ (r & 7)) << 4);
                const __half* gp = vB + (size_t)r * NPIX + n0 + u * 8;
                asm volatile("cp.async.cg.shared.global [%0], [%1], 16;\n"
                             :: "r"(dst), "l"(gp));
            }
        }
        asm volatile("cp.async.commit_group;\n");

        uint32_t kb = sb + FST + buf * FSTG;
        uint32_t vb = kb + FVO;

        #pragma unroll
        for (int mt = 0; mt < 2; mt++) {
            float sa[4][4];
            #pragma unroll
            for (int a = 0; a < 4; a++)
                #pragma unroll
                for (int c = 0; c < 4; c++) sa[a][c] = 0.f;

            #pragma unroll
            for (int ks = 0; ks < CQ / 16; ks++) {
                int c0 = ks * 2;
                uint32_t af[4];
                {
                    int lr = wmS + mt * 16 + (lane & 15);
                    int lc = c0 + (lane >> 4);
                    LDMX4(af[0], af[1], af[2], af[3],
                          sb + FSQ + lr * 128 + ((lc ^ (lr & 7)) << 4));
                }
                uint32_t bf[4][2];
                #pragma unroll
                for (int j = 0; j < 2; j++) {
                    int nb_ = wnS + j * 16;
                    int lr = nb_ + (lane & 7) + ((lane >> 4) << 3);
                    int lc = c0 + ((lane >> 3) & 1);
                    LDMX4(bf[2*j][0], bf[2*j][1], bf[2*j+1][0], bf[2*j+1][1],
                          kb + lr * 128 + ((lc ^ (lr & 7)) << 4));
                }
                #pragma unroll
                for (int nt = 0; nt < 4; nt++)
                    MMA16816(sa[nt], af, bf[nt][0], bf[nt][1]);
            }

            #pragma unroll
            for (int h = 0; h < 2; h++) {
                int rl = wmS + mt * 16 + g + h * 8;
                #pragma unroll
                for (int nt = 0; nt < 4; nt++) {
                    float e0 = __expf(sa[nt][h * 2 + 0] - ESHIFT);
                    float e1 = __expf(sa[nt][h * 2 + 1] - ESHIFT);
                    rsum[mt * 2 + h] += e0 + e1;
                    int u = (wnS >> 3) + nt;
                    *(__half2*)(smem + FSP + rl * 256 + ((u ^ (rl & 7)) << 4) + tg * 4)
                        = __floats2half2_rn(e0, e1);
                }
            }
        }
        __syncthreads();

        #pragma unroll
        for (int ks = 0; ks < 8; ks++) {
            int c0 = ks * 2;
            uint32_t af2[2][4];
            #pragma unroll
            for (int mt = 0; mt < 2; mt++) {
                int lr = wmS + mt * 16 + (lane & 15);
                int lc = c0 + (lane >> 4);
                LDMX4(af2[mt][0], af2[mt][1], af2[mt][2], af2[mt][3],
                      sb + FSP + lr * 256 + ((lc ^ (lr & 7)) << 4));
            }
            uint32_t bf2[8][2];
            #pragma unroll
            for (int j = 0; j < 4; j++) {
                int nb_ = wn2 + j * 16;
                int lr = nb_ + (lane & 7) + ((lane >> 4) << 3);
                int lc = c0 + ((lane >> 3) & 1);
                LDMX4(bf2[2*j][0], bf2[2*j][1], bf2[2*j+1][0], bf2[2*j+1][1],
                      vb + lr * 256 + ((lc ^ (lr & 7)) << 4));
            }
            #pragma unroll
            for (int mt = 0; mt < 2; mt++)
                #pragma unroll
                for (int nt = 0; nt < 8; nt++)
                    MMA16816(acc2[mt][nt], af2[mt], bf2[nt][0], bf2[nt][1]);
        }
        __syncthreads();
    }

    #pragma unroll
    for (int i = 0; i < 4; i++) {
        rsum[i] += __shfl_xor_sync(0xffffffffu, rsum[i], 1);
        rsum[i] += __shfl_xor_sync(0xffffffffu, rsum[i], 2);
    }
    float* rbuf = (float*)(smem + FRB);
    if (tg == 0) {
        #pragma unroll
        for (int mt = 0; mt < 2; mt++)
            #pragma unroll
            for (int h = 0; h < 2; h++)
                rbuf[(wid >> 2) * 128 + wmS + mt * 16 + g + h * 8] = rsum[mt * 2 + h];
    }
    __syncthreads();
    float* rinv = (float*)(smem + FRI);
    if (tid < 128) {
        float s = rbuf[tid] + rbuf[128 + tid] + rbuf[256 + tid] + rbuf[384 + tid];
        rinv[tid] = 1.f / s;
    }
    __syncthreads();

    float gam = *gammaP;
    const __half* RB_ = Res + ((size_t)bz * NPIX + m0) * Ctot + chunk * 256;
    __half* OB = Out + ((size_t)bz * NPIX + m0) * Ctot + chunk * 256;
    #pragma unroll
    for (int mt = 0; mt < 2; mt++)
    #pragma unroll
    for (int h = 0; h < 2; h++) {
        int rl = wmS + mt * 16 + g + h * 8;
        float is = gam * rinv[rl];
        #pragma unroll
        for (int nt = 0; nt < 8; nt++) {
            int cl = wn2 + nt * 8 + tg * 2;
            float2 rf = __half22float2(*(const __half2*)&RB_[(size_t)rl * Ctot + cl]);
            float v0 = acc2[mt][nt][h * 2 + 0] * is + rf.x;
            float v1 = acc2[mt][nt][h * 2 + 1] * is + rf.y;
            *(__half2*)&OB[(size_t)rl * Ctot + cl] = __floats2half2_rn(v0, v1);
        }
    }
}

// ---------------------------------------------------------------------------
// spectral norms (all 5, one block each)
// ---------------------------------------------------------------------------
__global__ void snorm_all(const float* __restrict__ W1, const float* __restrict__ u1,
                          const float* __restrict__ W2, const float* __restrict__ u2,
                          const float* __restrict__ W3, const float* __restrict__ u3,
                          const float* __restrict__ W4, const float* __restrict__ u4,
                          const float* __restrict__ W5, const float* __restrict__ u5,
                          float* __restrict__ sig)
{
    __shared__ float vs[512];
    __shared__ float us[512];
    __shared__ float red[256];
    __shared__ float red8[8];

    const float* W; const float* u; int O, C;
    switch (blockIdx.x) {
        case 0: W = W1; u = u1; O = 64;  C = 6;   break;
        case 1: W = W2; u = u2; O = 128; C = 64;  break;
        case 2: W = W3; u = u3; O = 256; C = 128; break;
        case 3: W = W4; u = u4; O = 512; C = 256; break;
        default: W = W5; u = u5; O = 1;  C = 512; break;
    }
    int t = threadIdx.x, lane = t & 31, wid = t >> 5;

    for (int o = t; o < O; o += 256) us[o] = u[o];
    __syncthreads();
    for (int c = t; c < C; c += 256) {
        float s = 0.f;
        #pragma unroll 4
        for (int o = 0; o < O; o++) s += W[(size_t)o * C + c] * us[o];
        vs[c] = s;
    }
    __syncthreads();
    float s = 0.f;
    for (int c = t; c < C; c += 256) s += vs[c] * vs[c];
    red[t] = s; __syncthreads();
    for (int off = 128; off > 0; off >>= 1) { if (t < off) red[t] += red[t + off]; __syncthreads(); }
    float vinv = 1.f / (sqrtf(red[0]) + 1e-12f);
    __syncthreads();
    for (int c = t; c < C; c += 256) vs[c] *= vinv;
    __syncthreads();
    float accq = 0.f;
    for (int o = wid; o < O; o += 8) {
        float tv = 0.f;
        for (int c = lane; c < C; c += 32) tv += W[(size_t)o * C + c] * vs[c];
        #pragma unroll
        for (int off = 16; off > 0; off >>= 1) tv += __shfl_xor_sync(0xffffffffu, tv, off);
        if (lane == 0) accq += tv * tv;
    }
    if (lane == 0) red8[wid] = accq;
    __syncthreads();
    if (t == 0) {
        float S = 0.f;
        #pragma unroll
        for (int w = 0; w < 8; w++) S += red8[w];
        float sigma = S / (sqrtf(S) + 1e-12f);
        sig[blockIdx.x] = 1.f / sigma;
    }
}

// ---------------------------------------------------------------------------
// weight prep: f32->fp16 (scaled W1..W5), concat [q|k|pad|v] buffers, biases.
// grid (13, 8)
// ---------------------------------------------------------------------------
__global__ void wprep(const float* W1, const float* W2, const float* W3,
                      const float* W4, const float* W5,
                      const float* q1, const float* k1, const float* v1,
                      const float* q2, const float* k2, const float* v2,
                      const float* qb1, const float* kb1,
                      const float* qb2, const float* kb2,
                      const float* sig,
                      __half* o0, __half* o1, __half* o2, __half* o3, __half* o4,
                      __half* qkv1, __half* qkv2,
                      float* d1, float* d2)
{
    if (blockIdx.x == 12) {
        if (blockIdx.y == 0) {
            int t = threadIdx.x;
            if (t < 128) d1[t] = (t < 32) ? qb1[t] : (t < 64 ? kb1[t - 32] : 0.f);
            else { int u = t - 128; d2[u] = (u < 64) ? qb2[u] : kb2[u - 64]; }
        }
        return;
    }
    const float* src; __half* dst; int O, C, Cp; float s = 1.f;
    switch (blockIdx.x) {
        case 0:  src = W1; dst = o0;                O = 64;  C = 6;   Cp = 8;   s = sig[0]; break;
        case 1:  src = W2; dst = o1;                O = 128; C = 64;  Cp = 64;  s = sig[1]; break;
        case 2:  src = W3; dst = o2;                O = 256; C = 128; Cp = 128; s = sig[2]; break;
        case 3:  src = W4; dst = o3;                O = 512; C = 256; Cp = 256; s = sig[3]; break;
        case 4:  src = W5; dst = o4;                O = 1;   C = 512; Cp = 512; s = sig[4]; break;
        case 5:  src = q1; dst = qkv1;              O = 32;  C = 256; Cp = 256; break;
        case 6:  src = k1; dst = qkv1 + 32 * 256;   O = 32;  C = 256; Cp = 256; break;
        case 7:  src = q1; dst = qkv1 + 64 * 256;   O = 64;  C = 0;   Cp = 256; break; // zero pad
        case 8:  src = v1; dst = qkv1 + 128 * 256;  O = 256; C = 256; Cp = 256; break;
        case 9:  src = q2; dst = qkv2;              O = 64;  C = 512; Cp = 512; break;
        case 10: src = k2; dst = qkv2 + 64 * 512;   O = 64;  C = 512; Cp = 512; break;
        default: src = v2; dst = qkv2 + 128 * 512;  O = 512; C = 512; Cp = 512; break;
    }
    int total = O * Cp;
    for (int i = blockIdx.y * 256 + threadIdx.x; i < total; i += 8 * 256) {
        int o = i / Cp, c = i % Cp;
        float v = (c < C) ? src[(size_t)o * C + c] * s : 0.f;
        dst[i] = __float2half(v);
    }
}

__global__ void tin(const float* __restrict__ in, __half* __restrict__ out) {
    int b = blockIdx.y;
    int p = blockIdx.x * 256 + threadIdx.x;
    const float* s = in + (size_t)b * 6 * NPIX + p;
    __half h[8];
    #pragma unroll
    for (int c = 0; c < 6; c++) h[c] = __float2half(s[(size_t)c * NPIX]);
    h[6] = __float2half(0.f);
    h[7] = __float2half(0.f);
    *(uint4*)(out + ((size_t)b * NPIX + p) * 8) = *(uint4*)h;
}

// ---------------------------------------------------------------------------
// kernel_launch
// ---------------------------------------------------------------------------
extern "C" void kernel_launch(void* const* d_in, const int* in_sizes, int n_in,
                              void* d_out, int out_size)
{
    const float* inp  = (const float*)d_in[0];
    const float* W1 = (const float*)d_in[1];  const float* b1 = (const float*)d_in[2];  const float* u1 = (const float*)d_in[3];
    const float* W2 = (const float*)d_in[4];  const float* b2 = (const float*)d_in[5];  const float* u2 = (const float*)d_in[6];
    const float* W3 = (const float*)d_in[7];  const float* b3 = (const float*)d_in[8];  const float* u3 = (const float*)d_in[9];
    const float* W4 = (const float*)d_in[10]; const float* b4 = (const float*)d_in[11]; const float* u4 = (const float*)d_in[12];
    const float* W5 = (const float*)d_in[13]; const float* b5 = (const float*)d_in[14]; const float* u5 = (const float*)d_in[15];
    const float* a1qW = (const float*)d_in[16]; const float* a1qb = (const float*)d_in[17];
    const float* a1kW = (const float*)d_in[18]; const float* a1kb = (const float*)d_in[19];
    const float* a1vW = (const float*)d_in[20]; const float* a1vb = (const float*)d_in[21];
    const float* a1g  = (const float*)d_in[22];
    const float* a2qW = (const float*)d_in[23]; const float* a2qb = (const float*)d_in[24];
    const float* a2kW = (const float*)d_in[25]; const float* a2kb = (const float*)d_in[26];
    const float* a2vW = (const float*)d_in[27]; const float* a2vb = (const float*)d_in[28];
    const float* a2g  = (const float*)d_in[29];

    __half *inTh, *a1h, *a2h, *a3h, *qkh, *vh, *t1h, *t2h, *a4h;
    __half *W1h, *W2h, *W3h, *W4h, *W5h, *qkv1h, *qkv2h;
    float *sig, *qkb1, *qkb2;
    cudaGetSymbolAddress((void**)&inTh, g_inT);
    cudaGetSymbolAddress((void**)&a1h, g_a1);
    cudaGetSymbolAddress((void**)&a2h, g_a2);
    cudaGetSymbolAddress((void**)&a3h, g_a3);
    cudaGetSymbolAddress((void**)&qkh, g_qk);
    cudaGetSymbolAddress((void**)&vh,  g_v);
    cudaGetSymbolAddress((void**)&t1h, g_t1);
    cudaGetSymbolAddress((void**)&t2h, g_t2);
    cudaGetSymbolAddress((void**)&a4h, g_a4);
    cudaGetSymbolAddress((void**)&sig, g_sig);
    cudaGetSymbolAddress((void**)&qkb1, g_qkb1);
    cudaGetSymbolAddress((void**)&qkb2, g_qkb2);
    cudaGetSymbolAddress((void**)&W1h, g_W1h);
    cudaGetSymbolAddress((void**)&W2h, g_W2h);
    cudaGetSymbolAddress((void**)&W3h, g_W3h);
    cudaGetSymbolAddress((void**)&W4h, g_W4h);
    cudaGetSymbolAddress((void**)&W5h, g_W5h);
    cudaGetSymbolAddress((void**)&qkv1h, g_qkv1h);
    cudaGetSymbolAddress((void**)&qkv2h, g_qkv2h);

    const int SMEMSZ = 98304;
    cudaFuncSetAttribute(hgemm<0>, cudaFuncAttributeMaxDynamicSharedMemorySize, SMEMSZ);
    cudaFuncSetAttribute(hgemm<5>, cudaFuncAttributeMaxDynamicSharedMemorySize, SMEMSZ);
    cudaFuncSetAttribute(hgemm<7>, cudaFuncAttributeMaxDynamicSharedMemorySize, SMEMSZ);
    cudaFuncSetAttribute(flash<32>, cudaFuncAttributeMaxDynamicSharedMemorySize, FSMEM);
    cudaFuncSetAttribute(flash<64>, cudaFuncAttributeMaxDynamicSharedMemorySize, FSMEM);

    const size_t NP = NPIX;
    auto gd = [&](int Nn) { return dim3((Nn + 127) / 128, NPIX / 128, BATCH); };

    snorm_all<<<5, 256>>>(W1, u1, W2, u2, W3, u3, W4, u4, W5, u5, sig);
    wprep<<<dim3(13, 8), 256>>>(W1, W2, W3, W4, W5, a1qW, a1kW, a1vW, a2qW, a2kW, a2vW,
                                a1qb, a1kb, a2qb, a2kb, sig,
                                W1h, W2h, W3h, W4h, W5h, qkv1h, qkv2h, qkb1, qkb2);
    tin<<<dim3(16, BATCH), 256>>>(inp, inTh);

    // conv1/2/3
    hgemm<0><<<gd(64), 256, SMEMSZ>>>(inTh, W1h, a1h, nullptr, nullptr, NPIX, 64, 8, 8, 8, 64,
        NP * 8, 0, NP * 64, 0, 0, b1, nullptr);
    hgemm<0><<<gd(128), 256, SMEMSZ>>>(a1h, W2h, a2h, nullptr, nullptr, NPIX, 128, 64, 64, 64, 128,
        NP * 64, 0, NP * 128, 0, 0, b2, nullptr);
    hgemm<0><<<gd(256), 256, SMEMSZ>>>(a2h, W3h, a3h, nullptr, nullptr, NPIX, 256, 128, 128, 128, 256,
        NP * 128, 0, NP * 256, 0, 0, b3, nullptr);

    // attention 1: merged q|k|v conv (N = 128 qk + 256 v), then flash
    hgemm<7><<<gd(384), 256, SMEMSZ>>>(a3h, qkv1h, qkh, vh, nullptr, NPIX, 384, 256, 256, 256, 128,
        NP * 256, 0, NP * 128, 256 * NP, 1, qkb1, a1vb);
    flash<32><<<dim3(1, 32, BATCH), 512, FSMEM>>>(qkh, vh, a3h, t1h, a1g, 256);

    // conv4
    hgemm<0><<<gd(512), 256, SMEMSZ>>>(t1h, W4h, a4h, nullptr, nullptr, NPIX, 512, 256, 256, 256, 512,
        NP * 256, 0, NP * 512, 0, 0, b4, nullptr);

    // attention 2: merged q|k|v conv (N = 128 qk + 512 v), then flash
    hgemm<7><<<gd(640), 256, SMEMSZ>>>(a4h, qkv2h, qkh, vh, nullptr, NPIX, 640, 512, 512, 512, 128,
        NP * 512, 0, NP * 128, 512 * NP, 1, qkb2, a2vb);
    flash<64><<<dim3(2, 32, BATCH), 512, FSMEM>>>(qkh, vh, a4h, t2h, a2g, 512);

    // conv5 -> f32 output (B, 4096)
    hgemm<5><<<gd(1), 256, SMEMSZ>>>(t2h, W5h, nullptr, nullptr, (float*)d_out, NPIX, 1, 512, 512, 512, 1,
        NP * 512, 0, NP, 0, 0, b5, nullptr);
}

// round 12
// speedup vs baseline: 1.2749x; 1.0113x over previous
#include <cuda_runtime.h>
#include <cuda_fp16.h>
#include <math.h>
#include <stdint.h>

// ---------------------------------------------------------------------------
// SpectralDiscriminator on GB300 — fp16 mma.sync GEMMs + flash-fused attention.
// R12: fused input-transpose+conv1 scalar kernel; conv5 as warp matvec.
// ---------------------------------------------------------------------------

#define NPIX 4096
#define BATCH 4
#define ESHIFT 4.0f

__device__ __half g_a1 [BATCH * NPIX * 64];
__device__ __half g_a2 [BATCH * NPIX * 128];
__device__ __half g_a3 [BATCH * NPIX * 256];
__device__ __half g_qk [BATCH * NPIX * 128];          // [pix][128]: q|k (+pad for attn1)
__device__ __half g_v  [BATCH * 512 * NPIX];          // channel-major [c][pix]
__device__ __half g_t1 [BATCH * NPIX * 256];
__device__ __half g_t2 [BATCH * NPIX * 512];
__device__ __half g_a4 [BATCH * NPIX * 512];
__device__ float g_sig[8];
__device__ float g_qkb1[128];
__device__ float g_qkb2[128];
__device__ __half g_W2h[128 * 64];
__device__ __half g_W3h[256 * 128];
__device__ __half g_W4h[512 * 256];
__device__ __half g_qkv1h[384 * 256];   // [q32|k32|pad64|v256] x 256
__device__ __half g_qkv2h[640 * 512];   // [q64|k64|v512] x 512

__device__ __forceinline__ uint32_t smem_u32(const void* p) {
    uint32_t a;
    asm("{ .reg .u64 t; cvta.to.shared.u64 t, %1; cvt.u32.u64 %0, t; }" : "=r"(a) : "l"(p));
    return a;
}

#define LDMX4(r0, r1, r2, r3, ad) \
    asm volatile("ldmatrix.sync.aligned.m8n8.x4.shared.b16 {%0,%1,%2,%3}, [%4];\n" \
        : "=r"(r0), "=r"(r1), "=r"(r2), "=r"(r3) : "r"(ad))

#define MMA16816(d, a, b0, b1) \
    asm volatile("mma.sync.aligned.m16n8k16.row.col.f32.f16.f16.f32 " \
        "{%0,%1,%2,%3}, {%4,%5,%6,%7}, {%8,%9}, {%0,%1,%2,%3};\n" \
        : "+f"((d)[0]), "+f"((d)[1]), "+f"((d)[2]), "+f"((d)[3]) \
        : "r"((a)[0]), "r"((a)[1]), "r"((a)[2]), "r"((a)[3]), "r"(b0), "r"(b1))

// cp.async one 128-row x 64-half tile into SW128 smem (128B rows)
__device__ __forceinline__ void cpa_tile(uint32_t dstBase, const __half* src, int ld,
                                         int Rall, int r0, int K, int k0, int tid) {
    #pragma unroll
    for (int i = 0; i < 4; i++) {
        int e = tid + i * 256;
        int r = e >> 3, c = e & 7;
        int gr = r0 + r;
        uint32_t dst = dstBase + r * 128 + ((c ^ (r & 7)) << 4);
        bool ok = (gr < Rall) && (k0 + c * 8 < K);
        const __half* g = src + (ok ? ((size_t)gr * ld + k0 + c * 8) : 0);
        int bytes = ok ? 16 : 0;
        asm volatile("cp.async.cg.shared.global [%0], [%1], 16, %2;\n"
                     :: "r"(dst), "l"(g), "r"(bytes));
    }
}

// ---------------------------------------------------------------------------
// fp16 GEMM: C[m][n] = sum_k A[m,k]*B[n,k]. x = n-tile (fast), y = m-tile.
// EPI: 0 leaky(acc+bias[n]) -> fp16
//      7 merged qkv: blockIdx.x < qkTiles -> acc+bias[n] plain to Ch (ldc);
//                    else -> acc+vbias transposed to C2[(n-128)*NPIX+m] via bounce
// ---------------------------------------------------------------------------
template<int EPI>
__global__ void __launch_bounds__(256, 2)
hgemm(const __half* __restrict__ A, const __half* __restrict__ B,
      __half* __restrict__ Ch, __half* __restrict__ C2,
      int Mall, int Nall, int K, int lda, int ldb, int ldc,
      size_t sA, size_t sB, size_t sC, size_t sC2, int qkTiles,
      const float* __restrict__ bias, const float* __restrict__ vbias)
{
    extern __shared__ char smem[];
    uint32_t sbase = smem_u32(smem);
    const uint32_t stageSz = 32768;

    int tid = threadIdx.x, lane = tid & 31, wid = tid >> 5;
    int bz = blockIdx.z;
    A += sA * bz;  B += sB * bz;

    int m0 = blockIdx.y * 128;
    int n0 = blockIdx.x * 128;
    int wm = (wid & 3) * 32;
    int wn = (wid >> 2) * 64;

    float acc[2][8][4];
    #pragma unroll
    for (int a = 0; a < 2; a++)
        #pragma unroll
        for (int b = 0; b < 8; b++)
            #pragma unroll
            for (int c = 0; c < 4; c++) acc[a][b][c] = 0.f;

    int nkt = (K + 63) >> 6;

    #pragma unroll
    for (int s = 0; s < 2; s++) {
        if (s < nkt) {
            uint32_t b = sbase + s * stageSz;
            cpa_tile(b, A, lda, Mall, m0, K, s * 64, tid);
            cpa_tile(b + 16384, B, ldb, Nall, n0, K, s * 64, tid);
        }
        asm volatile("cp.async.commit_group;\n");
    }

    for (int kt = 0; kt < nkt; kt++) {
        asm volatile("cp.async.wait_group 1;\n");
        __syncthreads();

        uint32_t Ab = sbase + (kt % 3) * stageSz;
        uint32_t Bb = Ab + 16384;

        int kl = K - kt * 64;
        int nks = (kl >= 64) ? 4 : ((kl + 15) >> 4);

        #pragma unroll 4
        for (int ks = 0; ks < nks; ks++) {
            int c0 = ks * 2;
            uint32_t af[2][4];
            #pragma unroll
            for (int mt = 0; mt < 2; mt++) {
                int lr = wm + mt * 16 + (lane & 15);
                int lc = c0 + (lane >> 4);
                LDMX4(af[mt][0], af[mt][1], af[mt][2], af[mt][3],
                      Ab + lr * 128 + ((lc ^ (lr & 7)) << 4));
            }
            uint32_t bf[8][2];
            #pragma unroll
            for (int j = 0; j < 4; j++) {
                int nb_ = wn + j * 16;
                int lr = nb_ + (lane & 7) + ((lane >> 4) << 3);
                int lc = c0 + ((lane >> 3) & 1);
                LDMX4(bf[2*j][0], bf[2*j][1], bf[2*j+1][0], bf[2*j+1][1],
                      Bb + lr * 128 + ((lc ^ (lr & 7)) << 4));
            }
            #pragma unroll
            for (int mt = 0; mt < 2; mt++)
                #pragma unroll
                for (int nt = 0; nt < 8; nt++)
                    MMA16816(acc[mt][nt], af[mt], bf[nt][0], bf[nt][1]);
        }

        int nx = kt + 2;
        if (nx < nkt) {
            uint32_t b = sbase + (nx % 3) * stageSz;
            cpa_tile(b, A, lda, Mall, m0, K, nx * 64, tid);
            cpa_tile(b + 16384, B, ldb, Nall, n0, K, nx * 64, tid);
        }
        asm volatile("cp.async.commit_group;\n");
    }

    int g = lane >> 2, tg = lane & 3;

    if (EPI == 7) {
        if ((int)blockIdx.x < qkTiles) {
            __half* Cp = Ch + sC * bz;
            #pragma unroll
            for (int mt = 0; mt < 2; mt++)
            #pragma unroll
            for (int h = 0; h < 2; h++) {
                int row = m0 + wm + mt * 16 + g + h * 8;
                #pragma unroll
                for (int nt = 0; nt < 8; nt++) {
                    int col = n0 + wn + nt * 8 + tg * 2;
                    float v0 = acc[mt][nt][h * 2 + 0] + bias[col];
                    float v1 = acc[mt][nt][h * 2 + 1] + bias[col + 1];
                    *(__half2*)&Cp[(size_t)row * ldc + col] = __floats2half2_rn(v0, v1);
                }
            }
        } else {
            int vbase = n0 - qkTiles * 128;
            asm volatile("cp.async.wait_group 0;\n");
            __syncthreads();
            float* st = (float*)smem;
            #pragma unroll
            for (int mt = 0; mt < 2; mt++)
            #pragma unroll
            for (int h = 0; h < 2; h++) {
                int rl = wm + mt * 16 + g + h * 8;
                #pragma unroll
                for (int nt = 0; nt < 8; nt++) {
                    int cl = wn + nt * 8 + tg * 2;
                    st[cl * 132 + rl]       = acc[mt][nt][h * 2 + 0] + vbias[vbase + cl];
                    st[(cl + 1) * 132 + rl] = acc[mt][nt][h * 2 + 1] + vbias[vbase + cl + 1];
                }
            }
            __syncthreads();
            int c = tid >> 1, ch = tid & 1;
            uint4 hb[8];
            __half* hbh = (__half*)hb;
            const float* sp = st + c * 132 + ch * 64;
            #pragma unroll
            for (int j = 0; j < 32; j++)
                ((__half2*)hbh)[j] = __floats2half2_rn(sp[2 * j], sp[2 * j + 1]);
            uint4* dp = (uint4*)&C2[sC2 * bz + (size_t)(vbase + c) * NPIX + m0 + ch * 64];
            #pragma unroll
            for (int jj = 0; jj < 8; jj++) dp[jj] = hb[jj];
        }
        return;
    }

    __half* Cp = Ch + sC * bz;
    #pragma unroll
    for (int mt = 0; mt < 2; mt++)
    #pragma unroll
    for (int h = 0; h < 2; h++) {
        int row = m0 + wm + mt * 16 + g + h * 8;
        #pragma unroll
        for (int nt = 0; nt < 8; nt++) {
            int col = n0 + wn + nt * 8 + tg * 2;
            float v0 = acc[mt][nt][h * 2 + 0];
            float v1 = acc[mt][nt][h * 2 + 1];
            if (col < Nall)     { v0 += bias[col];     v0 = v0 > 0.f ? v0 : 0.1f * v0; }
            if (col + 1 < Nall) { v1 += bias[col + 1]; v1 = v1 > 0.f ? v1 : 0.1f * v1; }
            if (col < Nall)
                *(__half2*)&Cp[(size_t)row * ldc + col] = __floats2half2_rn(v0, v1);
        }
    }
}

// ---------------------------------------------------------------------------
// Flash attention (unchanged from R11)
// ---------------------------------------------------------------------------
#define FSQ 0u
#define FSP 16384u
#define FST 49152u
#define FSTG 81920u
#define FVO 16384u
#define FRB 212992u
#define FRI (FRB + 2048u)
#define FSMEM (FRI + 512u)

template<int CQ>
__global__ void __launch_bounds__(512, 1)
flash(const __half* __restrict__ QK, const __half* __restrict__ V,
      const __half* __restrict__ Res, __half* __restrict__ Out,
      const float* __restrict__ gammaP, int Ctot)
{
    extern __shared__ char smem[];
    uint32_t sb = smem_u32(smem);
    int tid = threadIdx.x, lane = tid & 31, wid = tid >> 5;
    int g = lane >> 2, tg = lane & 3;
    int chunk = blockIdx.x, m0 = blockIdx.y * 128, bz = blockIdx.z;
    const int ldqk = 128;

    const __half* qkB = QK + (size_t)bz * NPIX * ldqk;
    const __half* vB  = V + (size_t)bz * Ctot * NPIX + (size_t)(chunk * 256) * NPIX;

    #pragma unroll
    for (int i = tid; i < 1024; i += 512) {
        int r = i >> 3, u = i & 7;
        uint32_t dst = sb + FSQ + r * 128 + ((u ^ (r & 7)) << 4);
        int ok = (u * 8 < CQ) ? 16 : 0;
        const __half* gp = qkB + (size_t)(m0 + r) * ldqk + u * 8;
        asm volatile("cp.async.cg.shared.global [%0], [%1], 16, %2;\n"
                     :: "r"(dst), "l"(gp), "r"(ok));
    }

    int wmS = (wid & 3) * 32, wnS = (wid >> 2) * 32;
    int wn2 = (wid >> 2) * 64;

    {
        uint32_t kb = sb + FST;
        #pragma unroll
        for (int i = tid; i < 1024; i += 512) {
            int r = i >> 3, u = i & 7;
            uint32_t dst = kb + r * 128 + ((u ^ (r & 7)) << 4);
            int ok = (u * 8 < CQ) ? 16 : 0;
            const __half* gp = qkB + (size_t)r * ldqk + CQ + u * 8;
            asm volatile("cp.async.cg.shared.global [%0], [%1], 16, %2;\n"
                         :: "r"(dst), "l"(gp), "r"(ok));
        }
        uint32_t vb = kb + FVO;
        #pragma unroll
        for (int i = tid; i < 4096; i += 512) {
            int r = i >> 4, u = i & 15;
            uint32_t dst = vb + r * 256 + ((u ^ (r & 7)) << 4);
            const __half* gp = vB + (size_t)r * NPIX + u * 8;
            asm volatile("cp.async.cg.shared.global [%0], [%1], 16;\n"
                         :: "r"(dst), "l"(gp));
        }
    }
    asm volatile("cp.async.commit_group;\n");

    float acc2[2][8][4];
    #pragma unroll
    for (int a = 0; a < 2; a++)
        #pragma unroll
        for (int b = 0; b < 8; b++)
            #pragma unroll
            for (int c = 0; c < 4; c++) acc2[a][b][c] = 0.f;
    float rsum[4] = {0.f, 0.f, 0.f, 0.f};

    for (int n = 0; n < 32; n++) {
        asm volatile("cp.async.wait_group 0;\n");
        __syncthreads();
        int buf = n & 1;

        if (n + 1 < 32) {
            uint32_t kb = sb + FST + (buf ^ 1) * FSTG;
            int n0 = (n + 1) * 128;
            #pragma unroll
            for (int i = tid; i < 1024; i += 512) {
                int r = i >> 3, u = i & 7;
                uint32_t dst = kb + r * 128 + ((u ^ (r & 7)) << 4);
                int ok = (u * 8 < CQ) ? 16 : 0;
                const __half* gp = qkB + (size_t)(n0 + r) * ldqk + CQ + u * 8;
                asm volatile("cp.async.cg.shared.global [%0], [%1], 16, %2;\n"
                             :: "r"(dst), "l"(gp), "r"(ok));
            }
            uint32_t vb = kb + FVO;
            #pragma unroll
            for (int i = tid; i < 4096; i += 512) {
                int r = i >> 4, u = i & 15;
                uint32_t dst = vb + r * 256 + ((u ^ (r & 7)) << 4);
                const __half* gp = vB + (size_t)r * NPIX + n0 + u * 8;
                asm volatile("cp.async.cg.shared.global [%0], [%1], 16;\n"
                             :: "r"(dst), "l"(gp));
            }
        }
        asm volatile("cp.async.commit_group;\n");

        uint32_t kb = sb + FST + buf * FSTG;
        uint32_t vb = kb + FVO;

        #pragma unroll
        for (int mt = 0; mt < 2; mt++) {
            float sa[4][4];
            #pragma unroll
            for (int a = 0; a < 4; a++)
                #pragma unroll
                for (int c = 0; c < 4; c++) sa[a][c] = 0.f;

            #pragma unroll
            for (int ks = 0; ks < CQ / 16; ks++) {
                int c0 = ks * 2;
                uint32_t af[4];
                {
                    int lr = wmS + mt * 16 + (lane & 15);
                    int lc = c0 + (lane >> 4);
                    LDMX4(af[0], af[1], af[2], af[3],
                          sb + FSQ + lr * 128 + ((lc ^ (lr & 7)) << 4));
                }
                uint32_t bf[4][2];
                #pragma unroll
                for (int j = 0; j < 2; j++) {
                    int nb_ = wnS + j * 16;
                    int lr = nb_ + (lane & 7) + ((lane >> 4) << 3);
                    int lc = c0 + ((lane >> 3) & 1);
                    LDMX4(bf[2*j][0], bf[2*j][1], bf[2*j+1][0], bf[2*j+1][1],
                          kb + lr * 128 + ((lc ^ (lr & 7)) << 4));
                }
                #pragma unroll
                for (int nt = 0; nt < 4; nt++)
                    MMA16816(sa[nt], af, bf[nt][0], bf[nt][1]);
            }

            #pragma unroll
            for (int h = 0; h < 2; h++) {
                int rl = wmS + mt * 16 + g + h * 8;
                #pragma unroll
                for (int nt = 0; nt < 4; nt++) {
                    float e0 = __expf(sa[nt][h * 2 + 0] - ESHIFT);
                    float e1 = __expf(sa[nt][h * 2 + 1] - ESHIFT);
                    rsum[mt * 2 + h] += e0 + e1;
                    int u = (wnS >> 3) + nt;
                    *(__half2*)(smem + FSP + rl * 256 + ((u ^ (rl & 7)) << 4) + tg * 4)
                        = __floats2half2_rn(e0, e1);
                }
            }
        }
        __syncthreads();

        #pragma unroll
        for (int ks = 0; ks < 8; ks++) {
            int c0 = ks * 2;
            uint32_t af2[2][4];
            #pragma unroll
            for (int mt = 0; mt < 2; mt++) {
                int lr = wmS + mt * 16 + (lane & 15);
                int lc = c0 + (lane >> 4);
                LDMX4(af2[mt][0], af2[mt][1], af2[mt][2], af2[mt][3],
                      sb + FSP + lr * 256 + ((lc ^ (lr & 7)) << 4));
            }
            uint32_t bf2[8][2];
            #pragma unroll
            for (int j = 0; j < 4; j++) {
                int nb_ = wn2 + j * 16;
                int lr = nb_ + (lane & 7) + ((lane >> 4) << 3);
                int lc = c0 + ((lane >> 3) & 1);
                LDMX4(bf2[2*j][0], bf2[2*j][1], bf2[2*j+1][0], bf2[2*j+1][1],
                      vb + lr * 256 + ((lc ^ (lr & 7)) << 4));
            }
            #pragma unroll
            for (int mt = 0; mt < 2; mt++)
                #pragma unroll
                for (int nt = 0; nt < 8; nt++)
                    MMA16816(acc2[mt][nt], af2[mt], bf2[nt][0], bf2[nt][1]);
        }
        __syncthreads();
    }

    #pragma unroll
    for (int i = 0; i < 4; i++) {
        rsum[i] += __shfl_xor_sync(0xffffffffu, rsum[i], 1);
        rsum[i] += __shfl_xor_sync(0xffffffffu, rsum[i], 2);
    }
    float* rbuf = (float*)(smem + FRB);
    if (tg == 0) {
        #pragma unroll
        for (int mt = 0; mt < 2; mt++)
            #pragma unroll
            for (int h = 0; h < 2; h++)
                rbuf[(wid >> 2) * 128 + wmS + mt * 16 + g + h * 8] = rsum[mt * 2 + h];
    }
    __syncthreads();
    float* rinv = (float*)(smem + FRI);
    if (tid < 128) {
        float s = rbuf[tid] + rbuf[128 + tid] + rbuf[256 + tid] + rbuf[384 + tid];
        rinv[tid] = 1.f / s;
    }
    __syncthreads();

    float gam = *gammaP;
    const __half* RB_ = Res + ((size_t)bz * NPIX + m0) * Ctot + chunk * 256;
    __half* OB = Out + ((size_t)bz * NPIX + m0) * Ctot + chunk * 256;
    #pragma unroll
    for (int mt = 0; mt < 2; mt++)
    #pragma unroll
    for (int h = 0; h < 2; h++) {
        int rl = wmS + mt * 16 + g + h * 8;
        float is = gam * rinv[rl];
        #pragma unroll
        for (int nt = 0; nt < 8; nt++) {
            int cl = wn2 + nt * 8 + tg * 2;
            float2 rf = __half22float2(*(const __half2*)&RB_[(size_t)rl * Ctot + cl]);
            float v0 = acc2[mt][nt][h * 2 + 0] * is + rf.x;
            float v1 = acc2[mt][nt][h * 2 + 1] * is + rf.y;
            *(__half2*)&OB[(size_t)rl * Ctot + cl] = __floats2half2_rn(v0, v1);
        }
    }
}

// ---------------------------------------------------------------------------
// fused input transpose + conv1: a1[p][o] = leaky(sig1*W1[o,:]·x[:,p] + b1[o])
// grid (16, BATCH), 256 thr
// ---------------------------------------------------------------------------
__global__ void tin_conv1(const float* __restrict__ in, const float* __restrict__ W1,
                          const float* __restrict__ b1, const float* __restrict__ sig,
                          __half* __restrict__ a1)
{
    __shared__ float ws[64 * 6];
    __shared__ float bs[64];
    int t = threadIdx.x;
    float s = sig[0];
    if (t < 64) bs[t] = b1[t];
    for (int i = t; i < 384; i += 256) ws[i] = W1[i] * s;
    __syncthreads();

    int b = blockIdx.y;
    int p = blockIdx.x * 256 + t;
    const float* x = in + (size_t)b * 6 * NPIX + p;
    float xv[6];
    #pragma unroll
    for (int c = 0; c < 6; c++) xv[c] = x[(size_t)c * NPIX];

    __half ho[64];
    #pragma unroll
    for (int o = 0; o < 64; o++) {
        float acc = bs[o];
        #pragma unroll
        for (int c = 0; c < 6; c++) acc += ws[o * 6 + c] * xv[c];
        acc = acc > 0.f ? acc : 0.1f * acc;
        ho[o] = __float2half(acc);
    }
    uint4* dst = (uint4*)(a1 + ((size_t)b * NPIX + p) * 64);
    #pragma unroll
    for (int i = 0; i < 8; i++) dst[i] = ((uint4*)ho)[i];
}

// ---------------------------------------------------------------------------
// conv5 matvec: out[r] = leaky(sig5 * W5 · t2[r,:] + b5), warp per row.
// grid 2048, 256 thr (8 warps); rows = BATCH*NPIX = 16384.
// ---------------------------------------------------------------------------
__global__ void conv5_mv(const __half* __restrict__ t2, const float* __restrict__ W5,
                         const float* __restrict__ b5, const float* __restrict__ sig,
                         float* __restrict__ out)
{
    __shared__ float ws[512];
    int t = threadIdx.x, lane = t & 31, w = t >> 5;
    float s = sig[4];
    for (int i = t; i < 512; i += 256) ws[i] = W5[i] * s;
    __syncthreads();

    int r = blockIdx.x * 8 + w;
    const __half* row = t2 + (size_t)r * 512;
    const uint4* rp = (const uint4*)(row + lane * 16);
    float acc = 0.f;
    #pragma unroll
    for (int q = 0; q < 2; q++) {
        uint4 pk = rp[q];
        const __half2* h2 = (const __half2*)&pk;
        #pragma unroll
        for (int j = 0; j < 4; j++) {
            float2 v = __half22float2(h2[j]);
            int c = lane * 16 + q * 8 + j * 2;
            acc += v.x * ws[c] + v.y * ws[c + 1];
        }
    }
    #pragma unroll
    for (int off = 16; off > 0; off >>= 1) acc += __shfl_xor_sync(0xffffffffu, acc, off);
    if (lane == 0) {
        float v = acc + b5[0];
        out[r] = v > 0.f ? v : 0.1f * v;
    }
}

// ---------------------------------------------------------------------------
// spectral norms (all 5, one block each)
// ---------------------------------------------------------------------------
__global__ void snorm_all(const float* __restrict__ W1, const float* __restrict__ u1,
                          const float* __restrict__ W2, const float* __restrict__ u2,
                          const float* __restrict__ W3, const float* __restrict__ u3,
                          const float* __restrict__ W4, const float* __restrict__ u4,
                          const float* __restrict__ W5, const float* __restrict__ u5,
                          float* __restrict__ sig)
{
    __shared__ float vs[512];
    __shared__ float us[512];
    __shared__ float red[256];
    __shared__ float red8[8];

    const float* W; const float* u; int O, C;
    switch (blockIdx.x) {
        case 0: W = W1; u = u1; O = 64;  C = 6;   break;
        case 1: W = W2; u = u2; O = 128; C = 64;  break;
        case 2: W = W3; u = u3; O = 256; C = 128; break;
        case 3: W = W4; u = u4; O = 512; C = 256; break;
        default: W = W5; u = u5; O = 1;  C = 512; break;
    }
    int t = threadIdx.x, lane = t & 31, wid = t >> 5;

    for (int o = t; o < O; o += 256) us[o] = u[o];
    __syncthreads();
    for (int c = t; c < C; c += 256) {
        float s = 0.f;
        #pragma unroll 4
        for (int o = 0; o < O; o++) s += W[(size_t)o * C + c] * us[o];
        vs[c] = s;
    }
    __syncthreads();
    float s = 0.f;
    for (int c = t; c < C; c += 256) s += vs[c] * vs[c];
    red[t] = s; __syncthreads();
    for (int off = 128; off > 0; off >>= 1) { if (t < off) red[t] += red[t + off]; __syncthreads(); }
    float vinv = 1.f / (sqrtf(red[0]) + 1e-12f);
    __syncthreads();
    for (int c = t; c < C; c += 256) vs[c] *= vinv;
    __syncthreads();
    float accq = 0.f;
    for (int o = wid; o < O; o += 8) {
        float tv = 0.f;
        for (int c = lane; c < C; c += 32) tv += W[(size_t)o * C + c] * vs[c];
        #pragma unroll
        for (int off = 16; off > 0; off >>= 1) tv += __shfl_xor_sync(0xffffffffu, tv, off);
        if (lane == 0) accq += tv * tv;
    }
    if (lane == 0) red8[wid] = accq;
    __syncthreads();
    if (t == 0) {
        float S = 0.f;
        #pragma unroll
        for (int w = 0; w < 8; w++) S += red8[w];
        float sigma = S / (sqrtf(S) + 1e-12f);
        sig[blockIdx.x] = 1.f / sigma;
    }
}

// ---------------------------------------------------------------------------
// weight prep: f32->fp16 (scaled W2..W4), concat [q|k|pad|v] buffers, biases.
// grid (10, 8)
// ---------------------------------------------------------------------------
__global__ void wprep(const float* W2, const float* W3, const float* W4,
                      const float* q1, const float* k1, const float* v1,
                      const float* q2, const float* k2, const float* v2,
                      const float* qb1, const float* kb1,
                      const float* qb2, const float* kb2,
                      const float* sig,
                      __half* o1, __half* o2, __half* o3,
                      __half* qkv1, __half* qkv2,
                      float* d1, float* d2)
{
    if (blockIdx.x == 9) {
        if (blockIdx.y == 0) {
            int t = threadIdx.x;
            if (t < 128) d1[t] = (t < 32) ? qb1[t] : (t < 64 ? kb1[t - 32] : 0.f);
            else { int u = t - 128; d2[u] = (u < 64) ? qb2[u] : kb2[u - 64]; }
        }
        return;
    }
    const float* src; __half* dst; int O, C, Cp; float s = 1.f;
    switch (blockIdx.x) {
        case 0:  src = W2; dst = o1;                O = 128; C = 64;  Cp = 64;  s = sig[1]; break;
        case 1:  src = W3; dst = o2;                O = 256; C = 128; Cp = 128; s = sig[2]; break;
        case 2:  src = W4; dst = o3;                O = 512; C = 256; Cp = 256; s = sig[3]; break;
        case 3:  src = q1; dst = qkv1;              O = 32;  C = 256; Cp = 256; break;
        case 4:  src = k1; dst = qkv1 + 32 * 256;   O = 32;  C = 256; Cp = 256; break;
        case 5:  src = q1; dst = qkv1 + 64 * 256;   O = 64;  C = 0;   Cp = 256; break; // zero pad
        case 6:  src = v1; dst = qkv1 + 128 * 256;  O = 256; C = 256; Cp = 256; break;
        case 7:  src = q2; dst = qkv2;              O = 64;  C = 512; Cp = 512; break;
        case 8:  src = k2; dst = qkv2 + 64 * 512;   O = 64;  C = 512; Cp = 512; break;
        default: src = v2; dst = qkv2 + 128 * 512;  O = 512; C = 512; Cp = 512; break;
    }
    int total = O * Cp;
    for (int i = blockIdx.y * 256 + threadIdx.x; i < total; i += 8 * 256) {
        int o = i / Cp, c = i % Cp;
        float v = (c < C) ? src[(size_t)o * C + c] * s : 0.f;
        dst[i] = __float2half(v);
    }
}

// note: case index 10 (v2) handled by `default` with grid (11,8); keep grid x=11
// (cases 0..8 named, 9 = biases, 10 = v2 via default)

// ---------------------------------------------------------------------------
// kernel_launch
// ---------------------------------------------------------------------------
extern "C" void kernel_launch(void* const* d_in, const int* in_sizes, int n_in,
                              void* d_out, int out_size)
{
    const float* inp  = (const float*)d_in[0];
    const float* W1 = (const float*)d_in[1];  const float* b1 = (const float*)d_in[2];  const float* u1 = (const float*)d_in[3];
    const float* W2 = (const float*)d_in[4];  const float* b2 = (const float*)d_in[5];  const float* u2 = (const float*)d_in[6];
    const float* W3 = (const float*)d_in[7];  const float* b3 = (const float*)d_in[8];  const float* u3 = (const float*)d_in[9];
    const float* W4 = (const float*)d_in[10]; const float* b4 = (const float*)d_in[11]; const float* u4 = (const float*)d_in[12];
    const float* W5 = (const float*)d_in[13]; const float* b5 = (const float*)d_in[14]; const float* u5 = (const float*)d_in[15];
    const float* a1qW = (const float*)d_in[16]; const float* a1qb = (const float*)d_in[17];
    const float* a1kW = (const float*)d_in[18]; const float* a1kb = (const float*)d_in[19];
    const float* a1vW = (const float*)d_in[20]; const float* a1vb = (const float*)d_in[21];
    const float* a1g  = (const float*)d_in[22];
    const float* a2qW = (const float*)d_in[23]; const float* a2qb = (const float*)d_in[24];
    const float* a2kW = (const float*)d_in[25]; const float* a2kb = (const float*)d_in[26];
    const float* a2vW = (const float*)d_in[27]; const float* a2vb = (const float*)d_in[28];
    const float* a2g  = (const float*)d_in[29];

    __half *a1h, *a2h, *a3h, *qkh, *vh, *t1h, *t2h, *a4h;
    __half *W2h, *W3h, *W4h, *qkv1h, *qkv2h;
    float *sig, *qkb1, *qkb2;
    cudaGetSymbolAddress((void**)&a1h, g_a1);
    cudaGetSymbolAddress((void**)&a2h, g_a2);
    cudaGetSymbolAddress((void**)&a3h, g_a3);
    cudaGetSymbolAddress((void**)&qkh, g_qk);
    cudaGetSymbolAddress((void**)&vh,  g_v);
    cudaGetSymbolAddress((void**)&t1h, g_t1);
    cudaGetSymbolAddress((void**)&t2h, g_t2);
    cudaGetSymbolAddress((void**)&a4h, g_a4);
    cudaGetSymbolAddress((void**)&sig, g_sig);
    cudaGetSymbolAddress((void**)&qkb1, g_qkb1);
    cudaGetSymbolAddress((void**)&qkb2, g_qkb2);
    cudaGetSymbolAddress((void**)&W2h, g_W2h);
    cudaGetSymbolAddress((void**)&W3h, g_W3h);
    cudaGetSymbolAddress((void**)&W4h, g_W4h);
    cudaGetSymbolAddress((void**)&qkv1h, g_qkv1h);
    cudaGetSymbolAddress((void**)&qkv2h, g_qkv2h);

    const int SMEMSZ = 98304;
    cudaFuncSetAttribute(hgemm<0>, cudaFuncAttributeMaxDynamicSharedMemorySize, SMEMSZ);
    cudaFuncSetAttribute(hgemm<7>, cudaFuncAttributeMaxDynamicSharedMemorySize, SMEMSZ);
    cudaFuncSetAttribute(flash<32>, cudaFuncAttributeMaxDynamicSharedMemorySize, FSMEM);
    cudaFuncSetAttribute(flash<64>, cudaFuncAttributeMaxDynamicSharedMemorySize, FSMEM);

    const size_t NP = NPIX;
    auto gd = [&](int Nn) { return dim3((Nn + 127) / 128, NPIX / 128, BATCH); };

    snorm_all<<<5, 256>>>(W1, u1, W2, u2, W3, u3, W4, u4, W5, u5, sig);
    wprep<<<dim3(11, 8), 256>>>(W2, W3, W4, a1qW, a1kW, a1vW, a2qW, a2kW, a2vW,
                                a1qb, a1kb, a2qb, a2kb, sig,
                                W2h, W3h, W4h, qkv1h, qkv2h, qkb1, qkb2);

    // fused transpose + conv1
    tin_conv1<<<dim3(16, BATCH), 256>>>(inp, W1, b1, sig, a1h);

    // conv2/3
    hgemm<0><<<gd(128), 256, SMEMSZ>>>(a1h, W2h, a2h, nullptr, NPIX, 128, 64, 64, 64, 128,
        NP * 64, 0, NP * 128, 0, 0, b2, nullptr);
    hgemm<0><<<gd(256), 256, SMEMSZ>>>(a2h, W3h, a3h, nullptr, NPIX, 256, 128, 128, 128, 256,
        NP * 128, 0, NP * 256, 0, 0, b3, nullptr);

    // attention 1: merged q|k|v conv (N = 128 qk + 256 v), then flash
    hgemm<7><<<gd(384), 256, SMEMSZ>>>(a3h, qkv1h, qkh, vh, NPIX, 384, 256, 256, 256, 128,
        NP * 256, 0, NP * 128, 256 * NP, 1, qkb1, a1vb);
    flash<32><<<dim3(1, 32, BATCH), 512, FSMEM>>>(qkh, vh, a3h, t1h, a1g, 256);

    // conv4
    hgemm<0><<<gd(512), 256, SMEMSZ>>>(t1h, W4h, a4h, nullptr, NPIX, 512, 256, 256, 256, 512,
        NP * 256, 0, NP * 512, 0, 0, b4, nullptr);

    // attention 2: merged q|k|v conv (N = 128 qk + 512 v), then flash
    hgemm<7><<<gd(640), 256, SMEMSZ>>>(a4h, qkv2h, qkh, vh, NPIX, 640, 512, 512, 512, 128,
        NP * 512, 0, NP * 128, 512 * NP, 1, qkb2, a2vb);
    flash<64><<<dim3(2, 32, BATCH), 512, FSMEM>>>(qkh, vh, a4h, t2h, a2g, 512);

    // conv5 -> f32 output (B, 4096) via warp matvec
    conv5_mv<<<2048, 256>>>(t2h, W5, b5, sig, (float*)d_out);
}

// round 13
// speedup vs baseline: 1.2754x; 1.0004x over previous
#include <cuda_runtime.h>
#include <cuda_fp16.h>
#include <math.h>
#include <stdint.h>

// ---------------------------------------------------------------------------
// SpectralDiscriminator on GB300 — fp16 mma.sync GEMMs + flash-fused attention.
// R13: conv2+conv3 fused into one CTA-resident two-stage GEMM kernel.
// ---------------------------------------------------------------------------

#define NPIX 4096
#define BATCH 4
#define ESHIFT 4.0f

__device__ __half g_a1 [BATCH * NPIX * 64];
__device__ __half g_a3 [BATCH * NPIX * 256];
__device__ __half g_qk [BATCH * NPIX * 128];          // [pix][128]: q|k (+pad for attn1)
__device__ __half g_v  [BATCH * 512 * NPIX];          // channel-major [c][pix]
__device__ __half g_t1 [BATCH * NPIX * 256];
__device__ __half g_t2 [BATCH * NPIX * 512];
__device__ __half g_a4 [BATCH * NPIX * 512];
__device__ float g_sig[8];
__device__ float g_qkb1[128];
__device__ float g_qkb2[128];
__device__ __half g_W2h[128 * 64];
__device__ __half g_W3h[256 * 128];
__device__ __half g_W4h[512 * 256];
__device__ __half g_qkv1h[384 * 256];   // [q32|k32|pad64|v256] x 256
__device__ __half g_qkv2h[640 * 512];   // [q64|k64|v512] x 512

__device__ __forceinline__ uint32_t smem_u32(const void* p) {
    uint32_t a;
    asm("{ .reg .u64 t; cvta.to.shared.u64 t, %1; cvt.u32.u64 %0, t; }" : "=r"(a) : "l"(p));
    return a;
}

#define LDMX4(r0, r1, r2, r3, ad) \
    asm volatile("ldmatrix.sync.aligned.m8n8.x4.shared.b16 {%0,%1,%2,%3}, [%4];\n" \
        : "=r"(r0), "=r"(r1), "=r"(r2), "=r"(r3) : "r"(ad))

#define MMA16816(d, a, b0, b1) \
    asm volatile("mma.sync.aligned.m16n8k16.row.col.f32.f16.f16.f32 " \
        "{%0,%1,%2,%3}, {%4,%5,%6,%7}, {%8,%9}, {%0,%1,%2,%3};\n" \
        : "+f"((d)[0]), "+f"((d)[1]), "+f"((d)[2]), "+f"((d)[3]) \
        : "r"((a)[0]), "r"((a)[1]), "r"((a)[2]), "r"((a)[3]), "r"(b0), "r"(b1))

#define CPA16(dst, src) \
    asm volatile("cp.async.cg.shared.global [%0], [%1], 16;\n" :: "r"(dst), "l"(src))

// cp.async one 128-row x 64-half tile into SW128 smem (128B rows)
__device__ __forceinline__ void cpa_tile(uint32_t dstBase, const __half* src, int ld,
                                         int Rall, int r0, int K, int k0, int tid) {
    #pragma unroll
    for (int i = 0; i < 4; i++) {
        int e = tid + i * 256;
        int r = e >> 3, c = e & 7;
        int gr = r0 + r;
        uint32_t dst = dstBase + r * 128 + ((c ^ (r & 7)) << 4);
        bool ok = (gr < Rall) && (k0 + c * 8 < K);
        const __half* g = src + (ok ? ((size_t)gr * ld + k0 + c * 8) : 0);
        int bytes = ok ? 16 : 0;
        asm volatile("cp.async.cg.shared.global [%0], [%1], 16, %2;\n"
                     :: "r"(dst), "l"(g), "r"(bytes));
    }
}

// ---------------------------------------------------------------------------
// fp16 GEMM: C[m][n] = sum_k A[m,k]*B[n,k]. x = n-tile (fast), y = m-tile.
// EPI: 0 leaky(acc+bias[n]) -> fp16
//      7 merged qkv: blockIdx.x < qkTiles -> acc+bias[n] plain to Ch (ldc);
//                    else -> acc+vbias transposed to C2[(n-128)*NPIX+m] via bounce
// ---------------------------------------------------------------------------
template<int EPI>
__global__ void __launch_bounds__(256, 2)
hgemm(const __half* __restrict__ A, const __half* __restrict__ B,
      __half* __restrict__ Ch, __half* __restrict__ C2,
      int Mall, int Nall, int K, int lda, int ldb, int ldc,
      size_t sA, size_t sB, size_t sC, size_t sC2, int qkTiles,
      const float* __restrict__ bias, const float* __restrict__ vbias)
{
    extern __shared__ char smem[];
    uint32_t sbase = smem_u32(smem);
    const uint32_t stageSz = 32768;

    int tid = threadIdx.x, lane = tid & 31, wid = tid >> 5;
    int bz = blockIdx.z;
    A += sA * bz;  B += sB * bz;

    int m0 = blockIdx.y * 128;
    int n0 = blockIdx.x * 128;
    int wm = (wid & 3) * 32;
    int wn = (wid >> 2) * 64;

    float acc[2][8][4];
    #pragma unroll
    for (int a = 0; a < 2; a++)
        #pragma unroll
        for (int b = 0; b < 8; b++)
            #pragma unroll
            for (int c = 0; c < 4; c++) acc[a][b][c] = 0.f;

    int nkt = (K + 63) >> 6;

    #pragma unroll
    for (int s = 0; s < 2; s++) {
        if (s < nkt) {
            uint32_t b = sbase + s * stageSz;
            cpa_tile(b, A, lda, Mall, m0, K, s * 64, tid);
            cpa_tile(b + 16384, B, ldb, Nall, n0, K, s * 64, tid);
        }
        asm volatile("cp.async.commit_group;\n");
    }

    for (int kt = 0; kt < nkt; kt++) {
        asm volatile("cp.async.wait_group 1;\n");
        __syncthreads();

        uint32_t Ab = sbase + (kt % 3) * stageSz;
        uint32_t Bb = Ab + 16384;

        int kl = K - kt * 64;
        int nks = (kl >= 64) ? 4 : ((kl + 15) >> 4);

        #pragma unroll 4
        for (int ks = 0; ks < nks; ks++) {
            int c0 = ks * 2;
            uint32_t af[2][4];
            #pragma unroll
            for (int mt = 0; mt < 2; mt++) {
                int lr = wm + mt * 16 + (lane & 15);
                int lc = c0 + (lane >> 4);
                LDMX4(af[mt][0], af[mt][1], af[mt][2], af[mt][3],
                      Ab + lr * 128 + ((lc ^ (lr & 7)) << 4));
            }
            uint32_t bf[8][2];
            #pragma unroll
            for (int j = 0; j < 4; j++) {
                int nb_ = wn + j * 16;
                int lr = nb_ + (lane & 7) + ((lane >> 4) << 3);
                int lc = c0 + ((lane >> 3) & 1);
                LDMX4(bf[2*j][0], bf[2*j][1], bf[2*j+1][0], bf[2*j+1][1],
                      Bb + lr * 128 + ((lc ^ (lr & 7)) << 4));
            }
            #pragma unroll
            for (int mt = 0; mt < 2; mt++)
                #pragma unroll
                for (int nt = 0; nt < 8; nt++)
                    MMA16816(acc[mt][nt], af[mt], bf[nt][0], bf[nt][1]);
        }

        int nx = kt + 2;
        if (nx < nkt) {
            uint32_t b = sbase + (nx % 3) * stageSz;
            cpa_tile(b, A, lda, Mall, m0, K, nx * 64, tid);
            cpa_tile(b + 16384, B, ldb, Nall, n0, K, nx * 64, tid);
        }
        asm volatile("cp.async.commit_group;\n");
    }

    int g = lane >> 2, tg = lane & 3;

    if (EPI == 7) {
        if ((int)blockIdx.x < qkTiles) {
            __half* Cp = Ch + sC * bz;
            #pragma unroll
            for (int mt = 0; mt < 2; mt++)
            #pragma unroll
            for (int h = 0; h < 2; h++) {
                int row = m0 + wm + mt * 16 + g + h * 8;
                #pragma unroll
                for (int nt = 0; nt < 8; nt++) {
                    int col = n0 + wn + nt * 8 + tg * 2;
                    float v0 = acc[mt][nt][h * 2 + 0] + bias[col];
                    float v1 = acc[mt][nt][h * 2 + 1] + bias[col + 1];
                    *(__half2*)&Cp[(size_t)row * ldc + col] = __floats2half2_rn(v0, v1);
                }
            }
        } else {
            int vbase = n0 - qkTiles * 128;
            asm volatile("cp.async.wait_group 0;\n");
            __syncthreads();
            float* st = (float*)smem;
            #pragma unroll
            for (int mt = 0; mt < 2; mt++)
            #pragma unroll
            for (int h = 0; h < 2; h++) {
                int rl = wm + mt * 16 + g + h * 8;
                #pragma unroll
                for (int nt = 0; nt < 8; nt++) {
                    int cl = wn + nt * 8 + tg * 2;
                    st[cl * 132 + rl]       = acc[mt][nt][h * 2 + 0] + vbias[vbase + cl];
                    st[(cl + 1) * 132 + rl] = acc[mt][nt][h * 2 + 1] + vbias[vbase + cl + 1];
                }
            }
            __syncthreads();
            int c = tid >> 1, ch = tid & 1;
            uint4 hb[8];
            __half* hbh = (__half*)hb;
            const float* sp = st + c * 132 + ch * 64;
            #pragma unroll
            for (int j = 0; j < 32; j++)
                ((__half2*)hbh)[j] = __floats2half2_rn(sp[2 * j], sp[2 * j + 1]);
            uint4* dp = (uint4*)&C2[sC2 * bz + (size_t)(vbase + c) * NPIX + m0 + ch * 64];
            #pragma unroll
            for (int jj = 0; jj < 8; jj++) dp[jj] = hb[jj];
        }
        return;
    }

    __half* Cp = Ch + sC * bz;
    #pragma unroll
    for (int mt = 0; mt < 2; mt++)
    #pragma unroll
    for (int h = 0; h < 2; h++) {
        int row = m0 + wm + mt * 16 + g + h * 8;
        #pragma unroll
        for (int nt = 0; nt < 8; nt++) {
            int col = n0 + wn + nt * 8 + tg * 2;
            float v0 = acc[mt][nt][h * 2 + 0];
            float v1 = acc[mt][nt][h * 2 + 1];
            if (col < Nall)     { v0 += bias[col];     v0 = v0 > 0.f ? v0 : 0.1f * v0; }
            if (col + 1 < Nall) { v1 += bias[col + 1]; v1 = v1 > 0.f ? v1 : 0.1f * v1; }
            if (col < Nall)
                *(__half2*)&Cp[(size_t)row * ldc + col] = __floats2half2_rn(v0, v1);
        }
    }
}

// ---------------------------------------------------------------------------
// Fused conv2+conv3: per CTA (m-tile of 128 pixels):
//   a2 = leaky(a1*W2^T + b2)   kept in smem (fp16, 256B rows)
//   a3 = leaky(a2*W3^T + b3)   written pixel-major
// grid (32, BATCH), 512 threads, smem 128KB.
// ---------------------------------------------------------------------------
__global__ void __launch_bounds__(512, 1)
conv23(const __half* __restrict__ A1, const __half* __restrict__ W2,
       const __half* __restrict__ W3, const float* __restrict__ b2,
       const float* __restrict__ b3, __half* __restrict__ A3)
{
    extern __shared__ char smem[];
    uint32_t sb = smem_u32(smem);
    const uint32_t W2o = 0, A1o = 16384, W3o = 32768, A2o = 98304;

    int tid = threadIdx.x, lane = tid & 31, wid = tid >> 5;
    int g = lane >> 2, tg = lane & 3;
    int m0 = blockIdx.x * 128, bz = blockIdx.y;
    const __half* a1B = A1 + ((size_t)bz * NPIX + m0) * 64;

    // ---- loads: W2 (1024 chunks), A1 tile (1024), W3 (4096)
    #pragma unroll
    for (int i = tid; i < 1024; i += 512) {
        int r = i >> 3, c = i & 7;
        CPA16(sb + W2o + r * 128 + ((c ^ (r & 7)) << 4), W2 + r * 64 + c * 8);
    }
    #pragma unroll
    for (int i = tid; i < 1024; i += 512) {
        int r = i >> 3, c = i & 7;
        CPA16(sb + A1o + r * 128 + ((c ^ (r & 7)) << 4), a1B + r * 64 + c * 8);
    }
    #pragma unroll
    for (int i = tid; i < 4096; i += 512) {
        int r = i >> 4, c = i & 15;
        CPA16(sb + W3o + r * 256 + ((c ^ (r & 7)) << 4), W3 + r * 128 + c * 8);
    }
    asm volatile("cp.async.commit_group;\n");
    asm volatile("cp.async.wait_group 0;\n");
    __syncthreads();

    int wm = (wid & 3) * 32;
    int wn1 = (wid >> 2) * 32;
    int wn2 = (wid >> 2) * 64;

    // ---- GEMM1: [128pix][128ch] = A1(K=64) x W2^T
    {
        float acc1[2][4][4];
        #pragma unroll
        for (int a = 0; a < 2; a++)
            #pragma unroll
            for (int b = 0; b < 4; b++)
                #pragma unroll
                for (int c = 0; c < 4; c++) acc1[a][b][c] = 0.f;

        #pragma unroll
        for (int ks = 0; ks < 4; ks++) {
            int c0 = ks * 2;
            uint32_t af[2][4];
            #pragma unroll
            for (int mt = 0; mt < 2; mt++) {
                int lr = wm + mt * 16 + (lane & 15);
                int lc = c0 + (lane >> 4);
                LDMX4(af[mt][0], af[mt][1], af[mt][2], af[mt][3],
                      sb + A1o + lr * 128 + ((lc ^ (lr & 7)) << 4));
            }
            uint32_t bf[4][2];
            #pragma unroll
            for (int j = 0; j < 2; j++) {
                int nb_ = wn1 + j * 16;
                int lr = nb_ + (lane & 7) + ((lane >> 4) << 3);
                int lc = c0 + ((lane >> 3) & 1);
                LDMX4(bf[2*j][0], bf[2*j][1], bf[2*j+1][0], bf[2*j+1][1],
                      sb + W2o + lr * 128 + ((lc ^ (lr & 7)) << 4));
            }
            #pragma unroll
            for (int mt = 0; mt < 2; mt++)
                #pragma unroll
                for (int nt = 0; nt < 4; nt++)
                    MMA16816(acc1[mt][nt], af[mt], bf[nt][0], bf[nt][1]);
        }

        // bias + leaky -> A2s (fp16, 256B rows, swizzled)
        #pragma unroll
        for (int mt = 0; mt < 2; mt++)
        #pragma unroll
        for (int h = 0; h < 2; h++) {
            int rl = wm + mt * 16 + g + h * 8;
            #pragma unroll
            for (int nt = 0; nt < 4; nt++) {
                int cl = wn1 + nt * 8 + tg * 2;
                float v0 = acc1[mt][nt][h * 2 + 0] + b2[cl];
                float v1 = acc1[mt][nt][h * 2 + 1] + b2[cl + 1];
                v0 = v0 > 0.f ? v0 : 0.1f * v0;
                v1 = v1 > 0.f ? v1 : 0.1f * v1;
                int u = cl >> 3;
                *(__half2*)(smem + A2o + rl * 256 + ((u ^ (rl & 7)) << 4) + tg * 4)
                    = __floats2half2_rn(v0, v1);
            }
        }
    }
    __syncthreads();

    // ---- GEMM2: [128pix][256ch] = A2(K=128) x W3^T
    float acc2[2][8][4];
    #pragma unroll
    for (int a = 0; a < 2; a++)
        #pragma unroll
        for (int b = 0; b < 8; b++)
            #pragma unroll
            for (int c = 0; c < 4; c++) acc2[a][b][c] = 0.f;

    #pragma unroll
    for (int ks = 0; ks < 8; ks++) {
        int c0 = ks * 2;
        uint32_t af2[2][4];
        #pragma unroll
        for (int mt = 0; mt < 2; mt++) {
            int lr = wm + mt * 16 + (lane & 15);
            int lc = c0 + (lane >> 4);
            LDMX4(af2[mt][0], af2[mt][1], af2[mt][2], af2[mt][3],
                  sb + A2o + lr * 256 + ((lc ^ (lr & 7)) << 4));
        }
        uint32_t bf2[8][2];
        #pragma unroll
        for (int j = 0; j < 4; j++) {
            int nb_ = wn2 + j * 16;
            int lr = nb_ + (lane & 7) + ((lane >> 4) << 3);
            int lc = c0 + ((lane >> 3) & 1);
            LDMX4(bf2[2*j][0], bf2[2*j][1], bf2[2*j+1][0], bf2[2*j+1][1],
                  sb + W3o + lr * 256 + ((lc ^ (lr & 7)) << 4));
        }
        #pragma unroll
        for (int mt = 0; mt < 2; mt++)
            #pragma unroll
            for (int nt = 0; nt < 8; nt++)
                MMA16816(acc2[mt][nt], af2[mt], bf2[nt][0], bf2[nt][1]);
    }

    __half* out = A3 + ((size_t)bz * NPIX + m0) * 256;
    #pragma unroll
    for (int mt = 0; mt < 2; mt++)
    #pragma unroll
    for (int h = 0; h < 2; h++) {
        int rl = wm + mt * 16 + g + h * 8;
        #pragma unroll
        for (int nt = 0; nt < 8; nt++) {
            int cl = wn2 + nt * 8 + tg * 2;
            float v0 = acc2[mt][nt][h * 2 + 0] + b3[cl];
            float v1 = acc2[mt][nt][h * 2 + 1] + b3[cl + 1];
            v0 = v0 > 0.f ? v0 : 0.1f * v0;
            v1 = v1 > 0.f ? v1 : 0.1f * v1;
            *(__half2*)&out[(size_t)rl * 256 + cl] = __floats2half2_rn(v0, v1);
        }
    }
}

// ---------------------------------------------------------------------------
// Flash attention (unchanged)
// ---------------------------------------------------------------------------
#define FSQ 0u
#define FSP 16384u
#define FST 49152u
#define FSTG 81920u
#define FVO 16384u
#define FRB 212992u
#define FRI (FRB + 2048u)
#define FSMEM (FRI + 512u)

template<int CQ>
__global__ void __launch_bounds__(512, 1)
flash(const __half* __restrict__ QK, const __half* __restrict__ V,
      const __half* __restrict__ Res, __half* __restrict__ Out,
      const float* __restrict__ gammaP, int Ctot)
{
    extern __shared__ char smem[];
    uint32_t sb = smem_u32(smem);
    int tid = threadIdx.x, lane = tid & 31, wid = tid >> 5;
    int g = lane >> 2, tg = lane & 3;
    int chunk = blockIdx.x, m0 = blockIdx.y * 128, bz = blockIdx.z;
    const int ldqk = 128;

    const __half* qkB = QK + (size_t)bz * NPIX * ldqk;
    const __half* vB  = V + (size_t)bz * Ctot * NPIX + (size_t)(chunk * 256) * NPIX;

    #pragma unroll
    for (int i = tid; i < 1024; i += 512) {
        int r = i >> 3, u = i & 7;
        uint32_t dst = sb + FSQ + r * 128 + ((u ^ (r & 7)) << 4);
        int ok = (u * 8 < CQ) ? 16 : 0;
        const __half* gp = qkB + (size_t)(m0 + r) * ldqk + u * 8;
        asm volatile("cp.async.cg.shared.global [%0], [%1], 16, %2;\n"
                     :: "r"(dst), "l"(gp), "r"(ok));
    }

    int wmS = (wid & 3) * 32, wnS = (wid >> 2) * 32;
    int wn2 = (wid >> 2) * 64;

    {
        uint32_t kb = sb + FST;
        #pragma unroll
        for (int i = tid; i < 1024; i += 512) {
            int r = i >> 3, u = i & 7;
            uint32_t dst = kb + r * 128 + ((u ^ (r & 7)) << 4);
            int ok = (u * 8 < CQ) ? 16 : 0;
            const __half* gp = qkB + (size_t)r * ldqk + CQ + u * 8;
            asm volatile("cp.async.cg.shared.global [%0], [%1], 16, %2;\n"
                         :: "r"(dst), "l"(gp), "r"(ok));
        }
        uint32_t vb = kb + FVO;
        #pragma unroll
        for (int i = tid; i < 4096; i += 512) {
            int r = i >> 4, u = i & 15;
            uint32_t dst = vb + r * 256 + ((u ^ (r & 7)) << 4);
            const __half* gp = vB + (size_t)r * NPIX + u * 8;
            CPA16(dst, gp);
        }
    }
    asm volatile("cp.async.commit_group;\n");

    float acc2[2][8][4];
    #pragma unroll
    for (int a = 0; a < 2; a++)
        #pragma unroll
        for (int b = 0; b < 8; b++)
            #pragma unroll
            for (int c = 0; c < 4; c++) acc2[a][b][c] = 0.f;
    float rsum[4] = {0.f, 0.f, 0.f, 0.f};

    for (int n = 0; n < 32; n++) {
        asm volatile("cp.async.wait_group 0;\n");
        __syncthreads();
        int buf = n & 1;

        if (n + 1 < 32) {
            uint32_t kb = sb + FST + (buf ^ 1) * FSTG;
            int n0 = (n + 1) * 128;
            #pragma unroll
            for (int i = tid; i < 1024; i += 512) {
                int r = i >> 3, u = i & 7;
                uint32_t dst = kb + r * 128 + ((u ^ (r & 7)) << 4);
                int ok = (u * 8 < CQ) ? 16 : 0;
                const __half* gp = qkB + (size_t)(n0 + r) * ldqk + CQ + u * 8;
                asm volatile("cp.async.cg.shared.global [%0], [%1], 16, %2;\n"
                             :: "r"(dst), "l"(gp), "r"(ok));
            }
            uint32_t vb = kb + FVO;
            #pragma unroll
            for (int i = tid; i < 4096; i += 512) {
                int r = i >> 4, u = i & 15;
                uint32_t dst = vb + r * 256 + ((u ^ (r & 7)) << 4);
                const __half* gp = vB + (size_t)r * NPIX + n0 + u * 8;
                CPA16(dst, gp);
            }
        }
        asm volatile("cp.async.commit_group;\n");

        uint32_t kb = sb + FST + buf * FSTG;
        uint32_t vb = kb + FVO;

        #pragma unroll
        for (int mt = 0; mt < 2; mt++) {
            float sa[4][4];
            #pragma unroll
            for (int a = 0; a < 4; a++)
                #pragma unroll
                for (int c = 0; c < 4; c++) sa[a][c] = 0.f;

            #pragma unroll
            for (int ks = 0; ks < CQ / 16; ks++) {
                int c0 = ks * 2;
                uint32_t af[4];
                {
                    int lr = wmS + mt * 16 + (lane & 15);
                    int lc = c0 + (lane >> 4);
                    LDMX4(af[0], af[1], af[2], af[3],
                          sb + FSQ + lr * 128 + ((lc ^ (lr & 7)) << 4));
                }
                uint32_t bf[4][2];
                #pragma unroll
                for (int j = 0; j < 2; j++) {
                    int nb_ = wnS + j * 16;
                    int lr = nb_ + (lane & 7) + ((lane >> 4) << 3);
                    int lc = c0 + ((lane >> 3) & 1);
                    LDMX4(bf[2*j][0], bf[2*j][1], bf[2*j+1][0], bf[2*j+1][1],
                          kb + lr * 128 + ((lc ^ (lr & 7)) << 4));
                }
                #pragma unroll
                for (int nt = 0; nt < 4; nt++)
                    MMA16816(sa[nt], af, bf[nt][0], bf[nt][1]);
            }

            #pragma unroll
            for (int h = 0; h < 2; h++) {
                int rl = wmS + mt * 16 + g + h * 8;
                #pragma unroll
                for (int nt = 0; nt < 4; nt++) {
                    float e0 = __expf(sa[nt][h * 2 + 0] - ESHIFT);
                    float e1 = __expf(sa[nt][h * 2 + 1] - ESHIFT);
                    rsum[mt * 2 + h] += e0 + e1;
                    int u = (wnS >> 3) + nt;
                    *(__half2*)(smem + FSP + rl * 256 + ((u ^ (rl & 7)) << 4) + tg * 4)
                        = __floats2half2_rn(e0, e1);
                }
            }
        }
        __syncthreads();

        #pragma unroll
        for (int ks = 0; ks < 8; ks++) {
            int c0 = ks * 2;
            uint32_t af2[2][4];
            #pragma unroll
            for (int mt = 0; mt < 2; mt++) {
                int lr = wmS + mt * 16 + (lane & 15);
                int lc = c0 + (lane >> 4);
                LDMX4(af2[mt][0], af2[mt][1], af2[mt][2], af2[mt][3],
                      sb + FSP + lr * 256 + ((lc ^ (lr & 7)) << 4));
            }
            uint32_t bf2[8][2];
            #pragma unroll
            for (int j = 0; j < 4; j++) {
                int nb_ = wn2 + j * 16;
                int lr = nb_ + (lane & 7) + ((lane >> 4) << 3);
                int lc = c0 + ((lane >> 3) & 1);
                LDMX4(bf2[2*j][0], bf2[2*j][1], bf2[2*j+1][0], bf2[2*j+1][1],
                      vb + lr * 256 + ((lc ^ (lr & 7)) << 4));
            }
            #pragma unroll
            for (int mt = 0; mt < 2; mt++)
                #pragma unroll
                for (int nt = 0; nt < 8; nt++)
                    MMA16816(acc2[mt][nt], af2[mt], bf2[nt][0], bf2[nt][1]);
        }
        __syncthreads();
    }

    #pragma unroll
    for (int i = 0; i < 4; i++) {
        rsum[i] += __shfl_xor_sync(0xffffffffu, rsum[i], 1);
        rsum[i] += __shfl_xor_sync(0xffffffffu, rsum[i], 2);
    }
    float* rbuf = (float*)(smem + FRB);
    if (tg == 0) {
        #pragma unroll
        for (int mt = 0; mt < 2; mt++)
            #pragma unroll
            for (int h = 0; h < 2; h++)
                rbuf[(wid >> 2) * 128 + wmS + mt * 16 + g + h * 8] = rsum[mt * 2 + h];
    }
    __syncthreads();
    float* rinv = (float*)(smem + FRI);
    if (tid < 128) {
        float s = rbuf[tid] + rbuf[128 + tid] + rbuf[256 + tid] + rbuf[384 + tid];
        rinv[tid] = 1.f / s;
    }
    __syncthreads();

    float gam = *gammaP;
    const __half* RB_ = Res + ((size_t)bz * NPIX + m0) * Ctot + chunk * 256;
    __half* OB = Out + ((size_t)bz * NPIX + m0) * Ctot + chunk * 256;
    #pragma unroll
    for (int mt = 0; mt < 2; mt++)
    #pragma unroll
    for (int h = 0; h < 2; h++) {
        int rl = wmS + mt * 16 + g + h * 8;
        float is = gam * rinv[rl];
        #pragma unroll
        for (int nt = 0; nt < 8; nt++) {
            int cl = wn2 + nt * 8 + tg * 2;
            float2 rf = __half22float2(*(const __half2*)&RB_[(size_t)rl * Ctot + cl]);
            float v0 = acc2[mt][nt][h * 2 + 0] * is + rf.x;
            float v1 = acc2[mt][nt][h * 2 + 1] * is + rf.y;
            *(__half2*)&OB[(size_t)rl * Ctot + cl] = __floats2half2_rn(v0, v1);
        }
    }
}

// ---------------------------------------------------------------------------
// fused input transpose + conv1
// ---------------------------------------------------------------------------
__global__ void tin_conv1(const float* __restrict__ in, const float* __restrict__ W1,
                          const float* __restrict__ b1, const float* __restrict__ sig,
                          __half* __restrict__ a1)
{
    __shared__ float ws[64 * 6];
    __shared__ float bs[64];
    int t = threadIdx.x;
    float s = sig[0];
    if (t < 64) bs[t] = b1[t];
    for (int i = t; i < 384; i += 256) ws[i] = W1[i] * s;
    __syncthreads();

    int b = blockIdx.y;
    int p = blockIdx.x * 256 + t;
    const float* x = in + (size_t)b * 6 * NPIX + p;
    float xv[6];
    #pragma unroll
    for (int c = 0; c < 6; c++) xv[c] = x[(size_t)c * NPIX];

    __half ho[64];
    #pragma unroll
    for (int o = 0; o < 64; o++) {
        float acc = bs[o];
        #pragma unroll
        for (int c = 0; c < 6; c++) acc += ws[o * 6 + c] * xv[c];
        acc = acc > 0.f ? acc : 0.1f * acc;
        ho[o] = __float2half(acc);
    }
    uint4* dst = (uint4*)(a1 + ((size_t)b * NPIX + p) * 64);
    #pragma unroll
    for (int i = 0; i < 8; i++) dst[i] = ((uint4*)ho)[i];
}

// ---------------------------------------------------------------------------
// conv5 matvec
// ---------------------------------------------------------------------------
__global__ void conv5_mv(const __half* __restrict__ t2, const float* __restrict__ W5,
                         const float* __restrict__ b5, const float* __restrict__ sig,
                         float* __restrict__ out)
{
    __shared__ float ws[512];
    int t = threadIdx.x, lane = t & 31, w = t >> 5;
    float s = sig[4];
    for (int i = t; i < 512; i += 256) ws[i] = W5[i] * s;
    __syncthreads();

    int r = blockIdx.x * 8 + w;
    const __half* row = t2 + (size_t)r * 512;
    const uint4* rp = (const uint4*)(row + lane * 16);
    float acc = 0.f;
    #pragma unroll
    for (int q = 0; q < 2; q++) {
        uint4 pk = rp[q];
        const __half2* h2 = (const __half2*)&pk;
        #pragma unroll
        for (int j = 0; j < 4; j++) {
            float2 v = __half22float2(h2[j]);
            int c = lane * 16 + q * 8 + j * 2;
            acc += v.x * ws[c] + v.y * ws[c + 1];
        }
    }
    #pragma unroll
    for (int off = 16; off > 0; off >>= 1) acc += __shfl_xor_sync(0xffffffffu, acc, off);
    if (lane == 0) {
        float v = acc + b5[0];
        out[r] = v > 0.f ? v : 0.1f * v;
    }
}

// ---------------------------------------------------------------------------
// spectral norms
// ---------------------------------------------------------------------------
__global__ void snorm_all(const float* __restrict__ W1, const float* __restrict__ u1,
                          const float* __restrict__ W2, const float* __restrict__ u2,
                          const float* __restrict__ W3, const float* __restrict__ u3,
                          const float* __restrict__ W4, const float* __restrict__ u4,
                          const float* __restrict__ W5, const float* __restrict__ u5,
                          float* __restrict__ sig)
{
    __shared__ float vs[512];
    __shared__ float us[512];
    __shared__ float red[256];
    __shared__ float red8[8];

    const float* W; const float* u; int O, C;
    switch (blockIdx.x) {
        case 0: W = W1; u = u1; O = 64;  C = 6;   break;
        case 1: W = W2; u = u2; O = 128; C = 64;  break;
        case 2: W = W3; u = u3; O = 256; C = 128; break;
        case 3: W = W4; u = u4; O = 512; C = 256; break;
        default: W = W5; u = u5; O = 1;  C = 512; break;
    }
    int t = threadIdx.x, lane = t & 31, wid = t >> 5;

    for (int o = t; o < O; o += 256) us[o] = u[o];
    __syncthreads();
    for (int c = t; c < C; c += 256) {
        float s = 0.f;
        #pragma unroll 4
        for (int o = 0; o < O; o++) s += W[(size_t)o * C + c] * us[o];
        vs[c] = s;
    }
    __syncthreads();
    float s = 0.f;
    for (int c = t; c < C; c += 256) s += vs[c] * vs[c];
    red[t] = s; __syncthreads();
    for (int off = 128; off > 0; off >>= 1) { if (t < off) red[t] += red[t + off]; __syncthreads(); }
    float vinv = 1.f / (sqrtf(red[0]) + 1e-12f);
    __syncthreads();
    for (int c = t; c < C; c += 256) vs[c] *= vinv;
    __syncthreads();
    float accq = 0.f;
    for (int o = wid; o < O; o += 8) {
        float tv = 0.f;
        for (int c = lane; c < C; c += 32) tv += W[(size_t)o * C + c] * vs[c];
        #pragma unroll
        for (int off = 16; off > 0; off >>= 1) tv += __shfl_xor_sync(0xffffffffu, tv, off);
        if (lane == 0) accq += tv * tv;
    }
    if (lane == 0) red8[wid] = accq;
    __syncthreads();
    if (t == 0) {
        float S = 0.f;
        #pragma unroll
        for (int w = 0; w < 8; w++) S += red8[w];
        float sigma = S / (sqrtf(S) + 1e-12f);
        sig[blockIdx.x] = 1.f / sigma;
    }
}

// ---------------------------------------------------------------------------
// weight prep
// ---------------------------------------------------------------------------
__global__ void wprep(const float* W2, const float* W3, const float* W4,
                      const float* q1, const float* k1, const float* v1,
                      const float* q2, const float* k2, const float* v2,
                      const float* qb1, const float* kb1,
                      const float* qb2, const float* kb2,
                      const float* sig,
                      __half* o1, __half* o2, __half* o3,
                      __half* qkv1, __half* qkv2,
                      float* d1, float* d2)
{
    if (blockIdx.x == 9) {
        if (blockIdx.y == 0) {
            int t = threadIdx.x;
            if (t < 128) d1[t] = (t < 32) ? qb1[t] : (t < 64 ? kb1[t - 32] : 0.f);
            else { int u = t - 128; d2[u] = (u < 64) ? qb2[u] : kb2[u - 64]; }
        }
        return;
    }
    const float* src; __half* dst; int O, C, Cp; float s = 1.f;
    switch (blockIdx.x) {
        case 0:  src = W2; dst = o1;                O = 128; C = 64;  Cp = 64;  s = sig[1]; break;
        case 1:  src = W3; dst = o2;                O = 256; C = 128; Cp = 128; s = sig[2]; break;
        case 2:  src = W4; dst = o3;                O = 512; C = 256; Cp = 256; s = sig[3]; break;
        case 3:  src = q1; dst = qkv1;              O = 32;  C = 256; Cp = 256; break;
        case 4:  src = k1; dst = qkv1 + 32 * 256;   O = 32;  C = 256; Cp = 256; break;
        case 5:  src = q1; dst = qkv1 + 64 * 256;   O = 64;  C = 0;   Cp = 256; break; // zero pad
        case 6:  src = v1; dst = qkv1 + 128 * 256;  O = 256; C = 256; Cp = 256; break;
        case 7:  src = q2; dst = qkv2;              O = 64;  C = 512; Cp = 512; break;
        case 8:  src = k2; dst = qkv2 + 64 * 512;   O = 64;  C = 512; Cp = 512; break;
        default: src = v2; dst = qkv2 + 128 * 512;  O = 512; C = 512; Cp = 512; break;
    }
    int total = O * Cp;
    for (int i = blockIdx.y * 256 + threadIdx.x; i < total; i += 8 * 256) {
        int o = i / Cp, c = i % Cp;
        float v = (c < C) ? src[(size_t)o * C + c] * s : 0.f;
        dst[i] = __float2half(v);
    }
}

// ---------------------------------------------------------------------------
// kernel_launch
// ---------------------------------------------------------------------------
extern "C" void kernel_launch(void* const* d_in, const int* in_sizes, int n_in,
                              void* d_out, int out_size)
{
    const float* inp  = (const float*)d_in[0];
    const float* W1 = (const float*)d_in[1];  const float* b1 = (const float*)d_in[2];  const float* u1 = (const float*)d_in[3];
    const float* W2 = (const float*)d_in[4];  const float* b2 = (const float*)d_in[5];  const float* u2 = (const float*)d_in[6];
    const float* W3 = (const float*)d_in[7];  const float* b3 = (const float*)d_in[8];  const float* u3 = (const float*)d_in[9];
    const float* W4 = (const float*)d_in[10]; const float* b4 = (const float*)d_in[11]; const float* u4 = (const float*)d_in[12];
    const float* W5 = (const float*)d_in[13]; const float* b5 = (const float*)d_in[14]; const float* u5 = (const float*)d_in[15];
    const float* a1qW = (const float*)d_in[16]; const float* a1qb = (const float*)d_in[17];
    const float* a1kW = (const float*)d_in[18]; const float* a1kb = (const float*)d_in[19];
    const float* a1vW = (const float*)d_in[20]; const float* a1vb = (const float*)d_in[21];
    const float* a1g  = (const float*)d_in[22];
    const float* a2qW = (const float*)d_in[23]; const float* a2qb = (const float*)d_in[24];
    const float* a2kW = (const float*)d_in[25]; const float* a2kb = (const float*)d_in[26];
    const float* a2vW = (const float*)d_in[27]; const float* a2vb = (const float*)d_in[28];
    const float* a2g  = (const float*)d_in[29];

    __half *a1h, *a3h, *qkh, *vh, *t1h, *t2h, *a4h;
    __half *W2h, *W3h, *W4h, *qkv1h, *qkv2h;
    float *sig, *qkb1, *qkb2;
    cudaGetSymbolAddress((void**)&a1h, g_a1);
    cudaGetSymbolAddress((void**)&a3h, g_a3);
    cudaGetSymbolAddress((void**)&qkh, g_qk);
    cudaGetSymbolAddress((void**)&vh,  g_v);
    cudaGetSymbolAddress((void**)&t1h, g_t1);
    cudaGetSymbolAddress((void**)&t2h, g_t2);
    cudaGetSymbolAddress((void**)&a4h, g_a4);
    cudaGetSymbolAddress((void**)&sig, g_sig);
    cudaGetSymbolAddress((void**)&qkb1, g_qkb1);
    cudaGetSymbolAddress((void**)&qkb2, g_qkb2);
    cudaGetSymbolAddress((void**)&W2h, g_W2h);
    cudaGetSymbolAddress((void**)&W3h, g_W3h);
    cudaGetSymbolAddress((void**)&W4h, g_W4h);
    cudaGetSymbolAddress((void**)&qkv1h, g_qkv1h);
    cudaGetSymbolAddress((void**)&qkv2h, g_qkv2h);

    const int SMEMSZ = 98304;
    const int C23SM = 131072;
    cudaFuncSetAttribute(hgemm<0>, cudaFuncAttributeMaxDynamicSharedMemorySize, SMEMSZ);
    cudaFuncSetAttribute(hgemm<7>, cudaFuncAttributeMaxDynamicSharedMemorySize, SMEMSZ);
    cudaFuncSetAttribute(conv23, cudaFuncAttributeMaxDynamicSharedMemorySize, C23SM);
    cudaFuncSetAttribute(flash<32>, cudaFuncAttributeMaxDynamicSharedMemorySize, FSMEM);
    cudaFuncSetAttribute(flash<64>, cudaFuncAttributeMaxDynamicSharedMemorySize, FSMEM);

    const size_t NP = NPIX;
    auto gd = [&](int Nn) { return dim3((Nn + 127) / 128, NPIX / 128, BATCH); };

    snorm_all<<<5, 256>>>(W1, u1, W2, u2, W3, u3, W4, u4, W5, u5, sig);
    wprep<<<dim3(11, 8), 256>>>(W2, W3, W4, a1qW, a1kW, a1vW, a2qW, a2kW, a2vW,
                                a1qb, a1kb, a2qb, a2kb, sig,
                                W2h, W3h, W4h, qkv1h, qkv2h, qkb1, qkb2);

    // fused transpose + conv1
    tin_conv1<<<dim3(16, BATCH), 256>>>(inp, W1, b1, sig, a1h);

    // fused conv2 + conv3
    conv23<<<dim3(32, BATCH), 512, C23SM>>>(a1h, W2h, W3h, b2, b3, a3h);

    // attention 1: merged q|k|v conv (N = 128 qk + 256 v), then flash
    hgemm<7><<<gd(384), 256, SMEMSZ>>>(a3h, qkv1h, qkh, vh, NPIX, 384, 256, 256, 256, 128,
        NP * 256, 0, NP * 128, 256 * NP, 1, qkb1, a1vb);
    flash<32><<<dim3(1, 32, BATCH), 512, FSMEM>>>(qkh, vh, a3h, t1h, a1g, 256);

    // conv4
    hgemm<0><<<gd(512), 256, SMEMSZ>>>(t1h, W4h, a4h, nullptr, NPIX, 512, 256, 256, 256, 512,
        NP * 256, 0, NP * 512, 0, 0, b4, nullptr);

    // attention 2: merged q|k|v conv (N = 128 qk + 512 v), then flash
    hgemm<7><<<gd(640), 256, SMEMSZ>>>(a4h, qkv2h, qkh, vh, NPIX, 640, 512, 512, 512, 128,
        NP * 512, 0, NP * 128, 512 * NP, 1, qkb2, a2vb);
    flash<64><<<dim3(2, 32, BATCH), 512, FSMEM>>>(qkh, vh, a4h, t2h, a2g, 512);

    // conv5 -> f32 output (B, 4096) via warp matvec
    conv5_mv<<<2048, 256>>>(t2h, W5, b5, sig, (float*)d_out);
}